// round 4
// baseline (speedup 1.0000x reference)
#include <cuda_runtime.h>
#include <math.h>

#define BATCH 8
#define SEQ   4096
#define IN    256
#define GDIM  1536      // 2*OUT*3
#define KDIM  512       // WINDOW*IN
#define ODIM  512       // 2*OUT
#define M_TOTAL (BATCH*SEQ)   // 32768

// Scratch for activated gates (z|f|o after tanh/sigmoid): 32768 x 1536 fp32 = 201MB
__device__ float g_act[(size_t)M_TOTAL * GDIM];

// ---------------------------------------------------------------------------
// GEMM + activation epilogue.
// Computes g[r, n] = sum_k win[r,k] * W[n,k] + bias[n], then
//   n <  512  -> tanh   (z)
//   n >= 512  -> sigmoid (f and o)
// win[r, k] = (k < 256) ? (s>0 ? x[r-1, k] : 0) : x[r, k-256]   where s = r % SEQ
// Tile: 128x128, Ktile=16, 256 threads, 8x8 per thread.
// ---------------------------------------------------------------------------
__global__ __launch_bounds__(256)
void gemm_act_kernel(const float* __restrict__ x,
                     const float* __restrict__ W,
                     const float* __restrict__ bias)
{
    __shared__ float As[16][132];
    __shared__ float Bs[16][132];

    const int row0 = blockIdx.y * 128;
    const int col0 = blockIdx.x * 128;
    const int tid  = threadIdx.x;
    const int tx   = tid & 15;   // n-dim
    const int ty   = tid >> 4;   // m-dim

    float acc[8][8];
    #pragma unroll
    for (int i = 0; i < 8; i++)
        #pragma unroll
        for (int j = 0; j < 8; j++)
            acc[i][j] = 0.f;

    for (int k0 = 0; k0 < KDIM; k0 += 16) {
        // ---- load A tile: 128 rows x 16 k, 2 float4 per thread ----
        #pragma unroll
        for (int q = 0; q < 2; q++) {
            int quad = tid + q * 256;       // 0..511
            int arow = quad >> 2;           // 0..127
            int kq   = (quad & 3) * 4;      // 0,4,8,12
            int r    = row0 + arow;
            float4 v;
            if (k0 < IN) {
                int s = r & (SEQ - 1);
                if (s == 0) {
                    v = make_float4(0.f, 0.f, 0.f, 0.f);
                } else {
                    v = *(const float4*)(x + (size_t)(r - 1) * IN + k0 + kq);
                }
            } else {
                v = *(const float4*)(x + (size_t)r * IN + (k0 - IN) + kq);
            }
            As[kq + 0][arow] = v.x;
            As[kq + 1][arow] = v.y;
            As[kq + 2][arow] = v.z;
            As[kq + 3][arow] = v.w;
        }
        // ---- load B tile: Bs[k][n] = W[(col0+n)*KDIM + k0 + k] ----
        #pragma unroll
        for (int q = 0; q < 2; q++) {
            int quad = tid + q * 256;
            int n    = quad >> 2;
            int kq   = (quad & 3) * 4;
            float4 v = *(const float4*)(W + (size_t)(col0 + n) * KDIM + k0 + kq);
            Bs[kq + 0][n] = v.x;
            Bs[kq + 1][n] = v.y;
            Bs[kq + 2][n] = v.z;
            Bs[kq + 3][n] = v.w;
        }
        __syncthreads();

        // ---- compute ----
        #pragma unroll
        for (int k = 0; k < 16; k++) {
            float a[8], b[8];
            *(float4*)&a[0] = *(const float4*)&As[k][ty * 8];
            *(float4*)&a[4] = *(const float4*)&As[k][ty * 8 + 4];
            *(float4*)&b[0] = *(const float4*)&Bs[k][tx * 8];
            *(float4*)&b[4] = *(const float4*)&Bs[k][tx * 8 + 4];
            #pragma unroll
            for (int i = 0; i < 8; i++)
                #pragma unroll
                for (int j = 0; j < 8; j++)
                    acc[i][j] = __fmaf_rn(a[i], b[j], acc[i][j]);
        }
        __syncthreads();
    }

    // ---- epilogue: bias + activation + store ----
    // col0 is a multiple of 128 and the z-section boundary (512) is a multiple
    // of 128, so the activation kind is uniform across the whole block.
    const bool is_tanh = (col0 < 512);
    float bv[8];
    #pragma unroll
    for (int j = 0; j < 8; j++)
        bv[j] = bias[col0 + tx * 8 + j];

    #pragma unroll
    for (int i = 0; i < 8; i++) {
        int grow = row0 + ty * 8 + i;
        float* dst = g_act + (size_t)grow * GDIM + col0 + tx * 8;
        float v[8];
        #pragma unroll
        for (int j = 0; j < 8; j++) {
            float t = acc[i][j] + bv[j];
            if (is_tanh) {
                v[j] = tanhf(t);
            } else {
                v[j] = 1.f / (1.f + __expf(-t));
            }
        }
        float4 s0 = make_float4(v[0], v[1], v[2], v[3]);
        float4 s1 = make_float4(v[4], v[5], v[6], v[7]);
        *(float4*)(dst)     = s0;
        *(float4*)(dst + 4) = s1;
    }
}

// ---------------------------------------------------------------------------
// Recurrent scan + output gating.
// 4096 channels: (b, dir, o). One thread per channel.
// grid = 128 blocks x 32 threads: blockIdx -> (b, dir, o-group of 32).
// forward (dir 0): c[s] = f*c[s-1] + (1-f)*z ; backward (dir 1): reversed.
// out[b, s, dir*256 + o] = sigmoid_o * c
// ---------------------------------------------------------------------------
__global__ __launch_bounds__(32)
void scan_kernel(float* __restrict__ out)
{
    const int idx  = blockIdx.x;          // 0..127
    const int b    = idx >> 4;            // 0..7
    const int rest = idx & 15;
    const int d    = rest >> 3;           // 0..1
    const int o    = ((rest & 7) << 5) + threadIdx.x;  // 0..255
    const int ch   = d * 256 + o;         // column within each 512-wide section

    const float* base  = g_act + (size_t)b * SEQ * GDIM;
    float*       obase = out   + (size_t)b * SEQ * ODIM;

    float c = 0.f;
    if (d == 0) {
        const float* p  = base + ch;
        float*       po = obase + ch;
        #pragma unroll 4
        for (int s = 0; s < SEQ; s++) {
            float z  = p[0];
            float f  = p[512];
            float so = p[1024];
            float t  = __fmaf_rn(-f, z, z);   // (1-f)*z, independent of c
            c = __fmaf_rn(f, c, t);           // single dependent FMA in chain
            *po = so * c;
            p  += GDIM;
            po += ODIM;
        }
    } else {
        const float* p  = base + (size_t)(SEQ - 1) * GDIM + ch;
        float*       po = obase + (size_t)(SEQ - 1) * ODIM + ch;
        #pragma unroll 4
        for (int s = 0; s < SEQ; s++) {
            float z  = p[0];
            float f  = p[512];
            float so = p[1024];
            float t  = __fmaf_rn(-f, z, z);
            c = __fmaf_rn(f, c, t);
            *po = so * c;
            p  -= GDIM;
            po -= ODIM;
        }
    }
}

extern "C" void kernel_launch(void* const* d_in, const int* in_sizes, int n_in,
                              void* d_out, int out_size)
{
    const float* x    = (const float*)d_in[0];  // (8, 4096, 256)
    const float* W    = (const float*)d_in[1];  // (1536, 512)
    const float* bias = (const float*)d_in[2];  // (1536,)
    float* out = (float*)d_out;                 // (8, 4096, 512)

    dim3 grid(GDIM / 128, M_TOTAL / 128);       // (12, 256)
    gemm_act_kernel<<<grid, 256>>>(x, W, bias);
    scan_kernel<<<128, 32>>>(out);
}

// round 7
// speedup vs baseline: 2.3182x; 2.3182x over previous
#include <cuda_runtime.h>
#include <cuda_bf16.h>
#include <math.h>

#define BATCH 8
#define SEQ   4096
#define IN    256
#define GDIM  1536      // 2*OUT*3
#define KDIM  512       // WINDOW*IN
#define ODIM  512       // 2*OUT
#define M_TOTAL (BATCH*SEQ)   // 32768
#define NCHUNK 64
#define CLEN   64       // SEQ / NCHUNK

// ---- device scratch ----
__device__ float          g_act[(size_t)M_TOTAL * GDIM];            // 201MB activated gates
__device__ float          g_Q  [(size_t)M_TOTAL * ODIM];            // 67MB  so * prefix-product
__device__ __nv_bfloat16  g_xhi[(size_t)M_TOTAL * IN];
__device__ __nv_bfloat16  g_xlo[(size_t)M_TOTAL * IN];
__device__ __nv_bfloat16  g_whi[(size_t)GDIM * KDIM];
__device__ __nv_bfloat16  g_wlo[(size_t)GDIM * KDIM];
__device__ float          g_A  [(size_t)BATCH * NCHUNK * ODIM];     // chunk f-product
__device__ float          g_B  [(size_t)BATCH * NCHUNK * ODIM];     // chunk local c end
__device__ float          g_C0 [(size_t)BATCH * NCHUNK * ODIM];     // chunk carry-in

// ---------------------------------------------------------------------------
// fp32 -> bf16 hi/lo split
// ---------------------------------------------------------------------------
__global__ void split_kernel(const float* __restrict__ src,
                             __nv_bfloat16* __restrict__ hi,
                             __nv_bfloat16* __restrict__ lo, int n4)
{
    int v = blockIdx.x * blockDim.x + threadIdx.x;
    if (v >= n4) return;
    float4 x = ((const float4*)src)[v];
    __nv_bfloat16 h0 = __float2bfloat16(x.x), h1 = __float2bfloat16(x.y);
    __nv_bfloat16 h2 = __float2bfloat16(x.z), h3 = __float2bfloat16(x.w);
    __nv_bfloat16 l0 = __float2bfloat16(x.x - __bfloat162float(h0));
    __nv_bfloat16 l1 = __float2bfloat16(x.y - __bfloat162float(h1));
    __nv_bfloat16 l2 = __float2bfloat16(x.z - __bfloat162float(h2));
    __nv_bfloat16 l3 = __float2bfloat16(x.w - __bfloat162float(h3));
    ushort4 hv = make_ushort4(__bfloat16_as_ushort(h0), __bfloat16_as_ushort(h1),
                              __bfloat16_as_ushort(h2), __bfloat16_as_ushort(h3));
    ushort4 lv = make_ushort4(__bfloat16_as_ushort(l0), __bfloat16_as_ushort(l1),
                              __bfloat16_as_ushort(l2), __bfloat16_as_ushort(l3));
    ((ushort4*)hi)[v] = hv;
    ((ushort4*)lo)[v] = lv;
}

// ---------------------------------------------------------------------------
// Tensor-core GEMM (bf16 split x3) + bias + activation epilogue.
// Block 128x128, K-tile 32, 256 threads = 8 warps (warp tile 64m x 32n).
// ---------------------------------------------------------------------------
__device__ __forceinline__ void mma16816(float* d, const unsigned* a, const unsigned* b)
{
    asm volatile(
        "mma.sync.aligned.m16n8k16.row.col.f32.bf16.bf16.f32 "
        "{%0,%1,%2,%3}, {%4,%5,%6,%7}, {%8,%9}, {%0,%1,%2,%3};\n"
        : "+f"(d[0]), "+f"(d[1]), "+f"(d[2]), "+f"(d[3])
        : "r"(a[0]), "r"(a[1]), "r"(a[2]), "r"(a[3]), "r"(b[0]), "r"(b[1]));
}

__global__ __launch_bounds__(256)
void gemm_tc_kernel(const float* __restrict__ bias)
{
    __shared__ __align__(16) unsigned short As_hi[128 * 32];
    __shared__ __align__(16) unsigned short As_lo[128 * 32];
    __shared__ __align__(16) unsigned short Bs_hi[128 * 32];
    __shared__ __align__(16) unsigned short Bs_lo[128 * 32];

    const int row0 = blockIdx.y * 128;
    const int col0 = blockIdx.x * 128;
    const int tid  = threadIdx.x;
    const int lane = tid & 31;
    const int w    = tid >> 5;
    const int wm   = (w & 1) * 64;     // warp m-offset
    const int wn   = (w >> 1) * 32;    // warp n-offset
    const int g    = lane >> 2;
    const int tig  = lane & 3;

    float acc[4][4][4];
    #pragma unroll
    for (int i = 0; i < 4; i++)
        #pragma unroll
        for (int j = 0; j < 4; j++)
            #pragma unroll
            for (int t = 0; t < 4; t++) acc[i][j][t] = 0.f;

    // per-fragment smem bases (swizzle value is identical for rows m and m+8)
    int a_base[4], a_sw[4], b_base[4], b_sw[4];
    #pragma unroll
    for (int mi = 0; mi < 4; mi++) {
        int m0 = wm + mi * 16 + g;
        a_base[mi] = m0 << 5;
        a_sw[mi]   = ((m0 >> 1) & 3) << 3;
    }
    #pragma unroll
    for (int ni = 0; ni < 4; ni++) {
        int n0 = wn + ni * 8 + g;
        b_base[ni] = n0 << 5;
        b_sw[ni]   = ((n0 >> 1) & 3) << 3;
    }

    const int ldm = tid >> 1;            // row handled by this thread on loads (x2 chunks)
    for (int kt = 0; kt < 16; kt++) {
        const int k0 = kt * 32;
        const bool shifted = (k0 < IN);
        const int  kcol    = k0 & (IN - 1);

        if (kt) __syncthreads();
        // ---- global -> smem (A: 2 chunks of 16B, B: 2 chunks of 16B, hi+lo) ----
        #pragma unroll
        for (int q = 0; q < 2; q++) {
            int c  = tid + q * 256;       // 0..511
            int m  = c >> 2;
            int qu = c & 3;
            int qs = qu ^ ((m >> 1) & 3); // swizzled quarter
            // A
            {
                int r = row0 + m;
                uint4 vh = make_uint4(0, 0, 0, 0), vl = vh;
                bool zero = shifted && ((r & (SEQ - 1)) == 0);
                if (!zero) {
                    size_t src = (size_t)(shifted ? (r - 1) : r) * IN + kcol + qu * 8;
                    vh = *(const uint4*)&g_xhi[src];
                    vl = *(const uint4*)&g_xlo[src];
                }
                int dst = m * 32 + qs * 8;
                *(uint4*)&As_hi[dst] = vh;
                *(uint4*)&As_lo[dst] = vl;
            }
            // B
            {
                int n = m;
                size_t src = (size_t)(col0 + n) * KDIM + k0 + qu * 8;
                uint4 vh = *(const uint4*)&g_whi[src];
                uint4 vl = *(const uint4*)&g_wlo[src];
                int dst = n * 32 + qs * 8;
                *(uint4*)&Bs_hi[dst] = vh;
                *(uint4*)&Bs_lo[dst] = vl;
            }
        }
        __syncthreads();

        // ---- compute: 2 x (m16n8k16) k-steps ----
        #pragma unroll
        for (int j = 0; j < 2; j++) {
            const int kb = j * 16 + tig * 2;
            unsigned ah[4][4], al[4][4], bh[4][2], bl[4][2];
            #pragma unroll
            for (int mi = 0; mi < 4; mi++) {
                int i0 = a_base[mi] + (kb ^ a_sw[mi]);
                int i2 = a_base[mi] + ((kb + 8) ^ a_sw[mi]);
                ah[mi][0] = *(const unsigned*)&As_hi[i0];
                ah[mi][1] = *(const unsigned*)&As_hi[i0 + 256];   // m+8 -> +8*32 elems
                ah[mi][2] = *(const unsigned*)&As_hi[i2];
                ah[mi][3] = *(const unsigned*)&As_hi[i2 + 256];
                al[mi][0] = *(const unsigned*)&As_lo[i0];
                al[mi][1] = *(const unsigned*)&As_lo[i0 + 256];
                al[mi][2] = *(const unsigned*)&As_lo[i2];
                al[mi][3] = *(const unsigned*)&As_lo[i2 + 256];
            }
            #pragma unroll
            for (int ni = 0; ni < 4; ni++) {
                int i0 = b_base[ni] + (kb ^ b_sw[ni]);
                int i1 = b_base[ni] + ((kb + 8) ^ b_sw[ni]);
                bh[ni][0] = *(const unsigned*)&Bs_hi[i0];
                bh[ni][1] = *(const unsigned*)&Bs_hi[i1];
                bl[ni][0] = *(const unsigned*)&Bs_lo[i0];
                bl[ni][1] = *(const unsigned*)&Bs_lo[i1];
            }
            #pragma unroll
            for (int mi = 0; mi < 4; mi++)
                #pragma unroll
                for (int ni = 0; ni < 4; ni++) {
                    mma16816(acc[mi][ni], ah[mi], bh[ni]);
                    mma16816(acc[mi][ni], ah[mi], bl[ni]);
                    mma16816(acc[mi][ni], al[mi], bh[ni]);
                }
        }
    }

    // ---- epilogue: bias + activation (block-uniform) + store ----
    const bool is_tanh = (col0 < 512);
    #pragma unroll
    for (int ni = 0; ni < 4; ni++) {
        int col = col0 + wn + ni * 8 + tig * 2;
        float b0 = bias[col], b1 = bias[col + 1];
        #pragma unroll
        for (int mi = 0; mi < 4; mi++) {
            int r0 = row0 + wm + mi * 16 + g;
            float v[4];
            v[0] = acc[mi][ni][0] + b0;
            v[1] = acc[mi][ni][1] + b1;
            v[2] = acc[mi][ni][2] + b0;
            v[3] = acc[mi][ni][3] + b1;
            #pragma unroll
            for (int t = 0; t < 4; t++)
                v[t] = is_tanh ? tanhf(v[t]) : (1.f / (1.f + __expf(-v[t])));
            *(float2*)&g_act[(size_t)r0 * GDIM + col]       = make_float2(v[0], v[1]);
            *(float2*)&g_act[(size_t)(r0 + 8) * GDIM + col] = make_float2(v[2], v[3]);
        }
    }
}

// ---------------------------------------------------------------------------
// Scan phase 1: chunk-local scan.  c_local with c0=0, P = inclusive prod(f).
// writes partial out = so*c_local and Q = so*P; chunk-end (P, c_local) to A/B.
// grid = (NCHUNK, BATCH), 512 threads (= channels; warps don't mix directions)
// ---------------------------------------------------------------------------
__global__ __launch_bounds__(512)
void scan_p1_kernel(float* __restrict__ out)
{
    const int ch = threadIdx.x;
    const int d  = ch >> 8;
    const int k  = blockIdx.x;
    const int b  = blockIdx.y;

    const int s0  = (k << 6) + (d ? (CLEN - 1) : 0);
    const int stp = d ? -1 : 1;
    const float* gp = g_act + (size_t)(b * SEQ + s0) * GDIM;
    float* op = out + (size_t)(b * SEQ + s0) * ODIM + ch;
    float* qp = g_Q + (size_t)(b * SEQ + s0) * ODIM + ch;
    const ptrdiff_t gst = (ptrdiff_t)stp * GDIM;
    const ptrdiff_t ost = (ptrdiff_t)stp * ODIM;

    float c = 0.f, P = 1.f;
    #pragma unroll 4
    for (int i = 0; i < CLEN; i++) {
        float z  = gp[ch];
        float f  = gp[512 + ch];
        float so = gp[1024 + ch];
        c = __fmaf_rn(f, c, __fmaf_rn(-f, z, z));
        P *= f;
        *op = so * c;
        *qp = so * P;
        gp += gst; op += ost; qp += ost;
    }
    size_t idx = (size_t)((b << 6) + k) * ODIM + ch;
    g_A[idx] = P;
    g_B[idx] = c;
}

// ---------------------------------------------------------------------------
// Scan phase 2: scan over chunk boundaries (64 per channel), stores carry-in.
// grid = BATCH blocks x 512 threads.
// ---------------------------------------------------------------------------
__global__ __launch_bounds__(512)
void scan_p2_kernel()
{
    const int ch = threadIdx.x;
    const int d  = ch >> 8;
    const int b  = blockIdx.x;
    float c0 = 0.f;
    if (d == 0) {
        for (int k = 0; k < NCHUNK; k++) {
            size_t idx = (size_t)((b << 6) + k) * ODIM + ch;
            g_C0[idx] = c0;
            c0 = __fmaf_rn(g_A[idx], c0, g_B[idx]);
        }
    } else {
        for (int k = NCHUNK - 1; k >= 0; k--) {
            size_t idx = (size_t)((b << 6) + k) * ODIM + ch;
            g_C0[idx] = c0;
            c0 = __fmaf_rn(g_A[idx], c0, g_B[idx]);
        }
    }
}

// ---------------------------------------------------------------------------
// Scan phase 3: out += Q * carry_in(chunk).  Vectorized float4.
// ---------------------------------------------------------------------------
__global__ __launch_bounds__(256)
void scan_p3_kernel(float* __restrict__ out)
{
    const int v   = blockIdx.x * 256 + threadIdx.x;   // float4 index
    const int row = v >> 7;                           // 128 float4 per 512-wide row
    const int c4  = (v & 127) << 2;                   // channel of .x
    const int b   = row >> 12;
    const int s   = row & (SEQ - 1);
    const int k   = s >> 6;

    float4 q  = ((const float4*)g_Q)[v];
    float4 c0 = *(const float4*)&g_C0[(size_t)((b << 6) + k) * ODIM + c4];
    float4 o  = ((const float4*)out)[v];
    o.x = __fmaf_rn(q.x, c0.x, o.x);
    o.y = __fmaf_rn(q.y, c0.y, o.y);
    o.z = __fmaf_rn(q.z, c0.z, o.z);
    o.w = __fmaf_rn(q.w, c0.w, o.w);
    ((float4*)out)[v] = o;
}

extern "C" void kernel_launch(void* const* d_in, const int* in_sizes, int n_in,
                              void* d_out, int out_size)
{
    const float* x    = (const float*)d_in[0];  // (8, 4096, 256)
    const float* W    = (const float*)d_in[1];  // (1536, 512)
    const float* bias = (const float*)d_in[2];  // (1536,)
    float* out = (float*)d_out;                 // (8, 4096, 512)

    __nv_bfloat16 *xhi, *xlo, *whi, *wlo;
    cudaGetSymbolAddress((void**)&xhi, g_xhi);
    cudaGetSymbolAddress((void**)&xlo, g_xlo);
    cudaGetSymbolAddress((void**)&whi, g_whi);
    cudaGetSymbolAddress((void**)&wlo, g_wlo);

    const int nx4 = (M_TOTAL * IN) / 4;        // 2,097,152
    const int nw4 = (GDIM * KDIM) / 4;         // 196,608
    split_kernel<<<(nx4 + 255) / 256, 256>>>(x, xhi, xlo, nx4);
    split_kernel<<<(nw4 + 255) / 256, 256>>>(W, whi, wlo, nw4);

    dim3 ggrid(GDIM / 128, M_TOTAL / 128);     // (12, 256)
    gemm_tc_kernel<<<ggrid, 256>>>(bias);

    scan_p1_kernel<<<dim3(NCHUNK, BATCH), 512>>>(out);
    scan_p2_kernel<<<BATCH, 512>>>();
    scan_p3_kernel<<<(M_TOTAL * ODIM / 4) / 256, 256>>>(out);
}

// round 9
// speedup vs baseline: 2.9045x; 1.2529x over previous
#include <cuda_runtime.h>
#include <cuda_bf16.h>
#include <math.h>
#include <stdint.h>

#define BATCH 8
#define SEQ   4096
#define IN    256
#define GDIM  1536      // 2*OUT*3
#define KDIM  512       // WINDOW*IN
#define ODIM  512       // 2*OUT
#define M_TOTAL (BATCH*SEQ)   // 32768
#define NCHUNK 64
#define CLEN   64       // SEQ / NCHUNK

// ---- GEMM tiling ----
#define BM 128
#define BN 128
#define BK 32
#define NKT (KDIM / BK)        // 16 k-tiles
#define NSTAGE 3
// per-stage smem regions (bytes): A hi 8K | A lo 8K | B hi 8K | B lo 8K
#define R_AHI 0
#define R_ALO 8192
#define R_BHI 16384
#define R_BLO 24576
#define STAGE_BYTES 32768
#define SMEM_DYN (NSTAGE * STAGE_BYTES)

// ---- device scratch ----
__device__ float          g_act[(size_t)M_TOTAL * GDIM];            // 201MB activated gates
__device__ float          g_Q  [(size_t)M_TOTAL * ODIM];            // 67MB  so * prefix-product
__device__ __nv_bfloat16  g_xhi[(size_t)M_TOTAL * IN];
__device__ __nv_bfloat16  g_xlo[(size_t)M_TOTAL * IN];
__device__ __nv_bfloat16  g_whi[(size_t)GDIM * KDIM];
__device__ __nv_bfloat16  g_wlo[(size_t)GDIM * KDIM];
__device__ float          g_A  [(size_t)BATCH * NCHUNK * ODIM];     // chunk f-product
__device__ float          g_B  [(size_t)BATCH * NCHUNK * ODIM];     // chunk local c end
__device__ float          g_C0 [(size_t)BATCH * NCHUNK * ODIM];     // chunk carry-in

// ---------------------------------------------------------------------------
// helpers
// ---------------------------------------------------------------------------
__device__ __forceinline__ uint32_t smem_u32(const void* p) {
    uint32_t a;
    asm("{ .reg .u64 t; cvta.to.shared.u64 t, %1; cvt.u32.u64 %0, t; }"
        : "=r"(a) : "l"(p));
    return a;
}

__device__ __forceinline__ void cp_async16(uint32_t dst, const void* src, int src_bytes) {
    asm volatile("cp.async.cg.shared.global [%0], [%1], 16, %2;"
                 :: "r"(dst), "l"(src), "r"(src_bytes));
}
__device__ __forceinline__ void cp_commit() {
    asm volatile("cp.async.commit_group;" ::: "memory");
}
template <int N>
__device__ __forceinline__ void cp_wait() {
    asm volatile("cp.async.wait_group %0;" :: "n"(N) : "memory");
}

__device__ __forceinline__ void mma16816(float* d, const unsigned* a, const unsigned* b)
{
    asm volatile(
        "mma.sync.aligned.m16n8k16.row.col.f32.bf16.bf16.f32 "
        "{%0,%1,%2,%3}, {%4,%5,%6,%7}, {%8,%9}, {%0,%1,%2,%3};\n"
        : "+f"(d[0]), "+f"(d[1]), "+f"(d[2]), "+f"(d[3])
        : "r"(a[0]), "r"(a[1]), "r"(a[2]), "r"(a[3]), "r"(b[0]), "r"(b[1]));
}

__device__ __forceinline__ float fsigmoid(float t) {
    return __fdividef(1.f, 1.f + __expf(-t));
}
__device__ __forceinline__ float ftanh_fast(float t) {
    return __fmaf_rn(2.f, __fdividef(1.f, 1.f + __expf(-2.f * t)), -1.f);
}

// ---------------------------------------------------------------------------
// fp32 -> bf16 hi/lo split
// ---------------------------------------------------------------------------
__global__ void split_kernel(const float* __restrict__ src,
                             __nv_bfloat16* __restrict__ hi,
                             __nv_bfloat16* __restrict__ lo, int n4)
{
    int v = blockIdx.x * blockDim.x + threadIdx.x;
    if (v >= n4) return;
    float4 x = ((const float4*)src)[v];
    __nv_bfloat16 h0 = __float2bfloat16(x.x), h1 = __float2bfloat16(x.y);
    __nv_bfloat16 h2 = __float2bfloat16(x.z), h3 = __float2bfloat16(x.w);
    __nv_bfloat16 l0 = __float2bfloat16(x.x - __bfloat162float(h0));
    __nv_bfloat16 l1 = __float2bfloat16(x.y - __bfloat162float(h1));
    __nv_bfloat16 l2 = __float2bfloat16(x.z - __bfloat162float(h2));
    __nv_bfloat16 l3 = __float2bfloat16(x.w - __bfloat162float(h3));
    ushort4 hv = make_ushort4(__bfloat16_as_ushort(h0), __bfloat16_as_ushort(h1),
                              __bfloat16_as_ushort(h2), __bfloat16_as_ushort(h3));
    ushort4 lv = make_ushort4(__bfloat16_as_ushort(l0), __bfloat16_as_ushort(l1),
                              __bfloat16_as_ushort(l2), __bfloat16_as_ushort(l3));
    ((ushort4*)hi)[v] = hv;
    ((ushort4*)lo)[v] = lv;
}

// ---------------------------------------------------------------------------
// Tensor-core GEMM (bf16 split x3), 3-stage cp.async pipeline.
// Block 128x128, K-tile 32, 256 threads = 8 warps (warp tile 64m x 32n).
// Swizzle/fragment mapping identical to the verified R7 kernel.
// ---------------------------------------------------------------------------
__global__ __launch_bounds__(256)
void gemm_tc_kernel(const float* __restrict__ bias)
{
    extern __shared__ __align__(128) char dyn[];
    const uint32_t sbase = smem_u32(dyn);

    const int row0 = blockIdx.y * BM;
    const int col0 = blockIdx.x * BN;
    const int tid  = threadIdx.x;
    const int lane = tid & 31;
    const int w    = tid >> 5;
    const int wm   = (w & 1) * 64;     // warp m-offset
    const int wn   = (w >> 1) * 32;    // warp n-offset
    const int g    = lane >> 2;
    const int tig  = lane & 3;

    float acc[4][4][4];
    #pragma unroll
    for (int i = 0; i < 4; i++)
        #pragma unroll
        for (int j = 0; j < 4; j++)
            #pragma unroll
            for (int t = 0; t < 4; t++) acc[i][j][t] = 0.f;

    // per-fragment smem element offsets (row stride 32 elems; swizzle per 2 rows)
    int a_base[4], a_sw[4], b_base[4], b_sw[4];
    #pragma unroll
    for (int mi = 0; mi < 4; mi++) {
        int m0 = wm + mi * 16 + g;
        a_base[mi] = m0 << 5;
        a_sw[mi]   = ((m0 >> 1) & 3) << 3;
    }
    #pragma unroll
    for (int ni = 0; ni < 4; ni++) {
        int n0 = wn + ni * 8 + g;
        b_base[ni] = n0 << 5;
        b_sw[ni]   = ((n0 >> 1) & 3) << 3;
    }

    // ---- loader lambda-equivalent (macro-ish): issues 8 cp.async of 16B ----
    // slot = tid + q*256 -> m = slot>>2 (0..127), qu = slot&3 (16B chunk),
    // dst quarter qs = qu ^ ((m>>1)&3); element row stride 32 (64B).
    const int l_m  = tid >> 2;
    const int l_qu = tid & 3;
    const int l_m2 = (tid + 256) >> 2;
    const int l_qu2 = (tid + 256) & 3;

    #define LOAD_STAGE(kt_, st_) do {                                         \
        const int  kg0     = (kt_) * BK;                                      \
        const bool shifted = (kg0 < IN);                                      \
        const int  kcol    = kg0 & (IN - 1);                                  \
        const uint32_t sb  = sbase + (st_) * STAGE_BYTES;                     \
        _Pragma("unroll")                                                     \
        for (int q = 0; q < 2; q++) {                                         \
            int m  = q ? l_m2 : l_m;                                          \
            int qu = q ? l_qu2 : l_qu;                                        \
            int qs = qu ^ ((m >> 1) & 3);                                     \
            /* A */                                                           \
            int r  = row0 + m;                                                \
            int zb = (shifted && ((r & (SEQ - 1)) == 0)) ? 0 : 16;            \
            int rs = r - (shifted ? 1 : 0);                                   \
            if (!zb) rs = r;                                                  \
            size_t asrc = (size_t)rs * IN + kcol + qu * 8;                    \
            uint32_t adst = sb + R_AHI + m * 64 + qs * 16;                    \
            cp_async16(adst,        g_xhi + asrc, zb);                        \
            cp_async16(adst + 8192, g_xlo + asrc, zb);                        \
            /* B */                                                           \
            size_t bsrc = (size_t)(col0 + m) * KDIM + kg0 + qu * 8;           \
            uint32_t bdst = sb + R_BHI + m * 64 + qs * 16;                    \
            cp_async16(bdst,        g_whi + bsrc, 16);                        \
            cp_async16(bdst + 8192, g_wlo + bsrc, 16);                        \
        }                                                                     \
    } while (0)

    // ---- prologue: prefetch k-tiles 0 and 1 ----
    LOAD_STAGE(0, 0); cp_commit();
    LOAD_STAGE(1, 1); cp_commit();

    int st = 0;
    for (int kt = 0; kt < NKT; kt++) {
        cp_wait<1>();              // group kt complete (kt+1 may be in flight)
        __syncthreads();           // stage st visible to all warps

        if (kt + 2 < NKT) {
            int st2 = st + 2; if (st2 >= NSTAGE) st2 -= NSTAGE;
            LOAD_STAGE(kt + 2, st2);
        }
        cp_commit();               // one group per iteration (possibly empty)

        const unsigned short* As_hi = (const unsigned short*)(dyn + st * STAGE_BYTES + R_AHI);
        const unsigned short* As_lo = (const unsigned short*)(dyn + st * STAGE_BYTES + R_ALO);
        const unsigned short* Bs_hi = (const unsigned short*)(dyn + st * STAGE_BYTES + R_BHI);
        const unsigned short* Bs_lo = (const unsigned short*)(dyn + st * STAGE_BYTES + R_BLO);

        #pragma unroll
        for (int j = 0; j < 2; j++) {
            const int kb = j * 16 + tig * 2;
            unsigned ah[4][4], al[4][4], bh[4][2], bl[4][2];
            #pragma unroll
            for (int mi = 0; mi < 4; mi++) {
                int i0 = a_base[mi] + (kb ^ a_sw[mi]);
                int i2 = a_base[mi] + ((kb + 8) ^ a_sw[mi]);
                ah[mi][0] = *(const unsigned*)&As_hi[i0];
                ah[mi][1] = *(const unsigned*)&As_hi[i0 + 256];   // m+8 -> +8*32 elems
                ah[mi][2] = *(const unsigned*)&As_hi[i2];
                ah[mi][3] = *(const unsigned*)&As_hi[i2 + 256];
                al[mi][0] = *(const unsigned*)&As_lo[i0];
                al[mi][1] = *(const unsigned*)&As_lo[i0 + 256];
                al[mi][2] = *(const unsigned*)&As_lo[i2];
                al[mi][3] = *(const unsigned*)&As_lo[i2 + 256];
            }
            #pragma unroll
            for (int ni = 0; ni < 4; ni++) {
                int i0 = b_base[ni] + (kb ^ b_sw[ni]);
                int i1 = b_base[ni] + ((kb + 8) ^ b_sw[ni]);
                bh[ni][0] = *(const unsigned*)&Bs_hi[i0];
                bh[ni][1] = *(const unsigned*)&Bs_hi[i1];
                bl[ni][0] = *(const unsigned*)&Bs_lo[i0];
                bl[ni][1] = *(const unsigned*)&Bs_lo[i1];
            }
            #pragma unroll
            for (int mi = 0; mi < 4; mi++)
                #pragma unroll
                for (int ni = 0; ni < 4; ni++) {
                    mma16816(acc[mi][ni], ah[mi], bh[ni]);
                    mma16816(acc[mi][ni], ah[mi], bl[ni]);
                    mma16816(acc[mi][ni], al[mi], bh[ni]);
                }
        }

        __syncthreads();           // all warps done with stage st before reuse
        st = st + 1; if (st >= NSTAGE) st = 0;
    }

    // ---- epilogue: bias + activation (block-uniform) + store ----
    const bool is_tanh = (col0 < 512);
    #pragma unroll
    for (int ni = 0; ni < 4; ni++) {
        int col = col0 + wn + ni * 8 + tig * 2;
        float b0 = bias[col], b1 = bias[col + 1];
        #pragma unroll
        for (int mi = 0; mi < 4; mi++) {
            int r0 = row0 + wm + mi * 16 + g;
            float v[4];
            v[0] = acc[mi][ni][0] + b0;
            v[1] = acc[mi][ni][1] + b1;
            v[2] = acc[mi][ni][2] + b0;
            v[3] = acc[mi][ni][3] + b1;
            #pragma unroll
            for (int t = 0; t < 4; t++)
                v[t] = is_tanh ? ftanh_fast(v[t]) : fsigmoid(v[t]);
            *(float2*)&g_act[(size_t)r0 * GDIM + col]       = make_float2(v[0], v[1]);
            *(float2*)&g_act[(size_t)(r0 + 8) * GDIM + col] = make_float2(v[2], v[3]);
        }
    }
}

// ---------------------------------------------------------------------------
// Scan phase 1: chunk-local scan.  c_local with c0=0, P = inclusive prod(f).
// ---------------------------------------------------------------------------
__global__ __launch_bounds__(512)
void scan_p1_kernel(float* __restrict__ out)
{
    const int ch = threadIdx.x;
    const int d  = ch >> 8;
    const int k  = blockIdx.x;
    const int b  = blockIdx.y;

    const int s0  = (k << 6) + (d ? (CLEN - 1) : 0);
    const int stp = d ? -1 : 1;
    const float* gp = g_act + (size_t)(b * SEQ + s0) * GDIM;
    float* op = out + (size_t)(b * SEQ + s0) * ODIM + ch;
    float* qp = g_Q + (size_t)(b * SEQ + s0) * ODIM + ch;
    const ptrdiff_t gst = (ptrdiff_t)stp * GDIM;
    const ptrdiff_t ost = (ptrdiff_t)stp * ODIM;

    float c = 0.f, P = 1.f;
    #pragma unroll 4
    for (int i = 0; i < CLEN; i++) {
        float z  = gp[ch];
        float f  = gp[512 + ch];
        float so = gp[1024 + ch];
        c = __fmaf_rn(f, c, __fmaf_rn(-f, z, z));
        P *= f;
        *op = so * c;
        *qp = so * P;
        gp += gst; op += ost; qp += ost;
    }
    size_t idx = (size_t)((b << 6) + k) * ODIM + ch;
    g_A[idx] = P;
    g_B[idx] = c;
}

// ---------------------------------------------------------------------------
// Scan phase 2: scan over chunk boundaries, stores carry-in.
// ---------------------------------------------------------------------------
__global__ __launch_bounds__(512)
void scan_p2_kernel()
{
    const int ch = threadIdx.x;
    const int d  = ch >> 8;
    const int b  = blockIdx.x;
    float c0 = 0.f;
    if (d == 0) {
        for (int k = 0; k < NCHUNK; k++) {
            size_t idx = (size_t)((b << 6) + k) * ODIM + ch;
            g_C0[idx] = c0;
            c0 = __fmaf_rn(g_A[idx], c0, g_B[idx]);
        }
    } else {
        for (int k = NCHUNK - 1; k >= 0; k--) {
            size_t idx = (size_t)((b << 6) + k) * ODIM + ch;
            g_C0[idx] = c0;
            c0 = __fmaf_rn(g_A[idx], c0, g_B[idx]);
        }
    }
}

// ---------------------------------------------------------------------------
// Scan phase 3: out += Q * carry_in(chunk).
// ---------------------------------------------------------------------------
__global__ __launch_bounds__(256)
void scan_p3_kernel(float* __restrict__ out)
{
    const int v   = blockIdx.x * 256 + threadIdx.x;   // float4 index
    const int row = v >> 7;
    const int c4  = (v & 127) << 2;
    const int b   = row >> 12;
    const int s   = row & (SEQ - 1);
    const int k   = s >> 6;

    float4 q  = ((const float4*)g_Q)[v];
    float4 c0 = *(const float4*)&g_C0[(size_t)((b << 6) + k) * ODIM + c4];
    float4 o  = ((const float4*)out)[v];
    o.x = __fmaf_rn(q.x, c0.x, o.x);
    o.y = __fmaf_rn(q.y, c0.y, o.y);
    o.z = __fmaf_rn(q.z, c0.z, o.z);
    o.w = __fmaf_rn(q.w, c0.w, o.w);
    ((float4*)out)[v] = o;
}

extern "C" void kernel_launch(void* const* d_in, const int* in_sizes, int n_in,
                              void* d_out, int out_size)
{
    const float* x    = (const float*)d_in[0];  // (8, 4096, 256)
    const float* W    = (const float*)d_in[1];  // (1536, 512)
    const float* bias = (const float*)d_in[2];  // (1536,)
    float* out = (float*)d_out;                 // (8, 4096, 512)

    __nv_bfloat16 *xhi, *xlo, *whi, *wlo;
    cudaGetSymbolAddress((void**)&xhi, g_xhi);
    cudaGetSymbolAddress((void**)&xlo, g_xlo);
    cudaGetSymbolAddress((void**)&whi, g_whi);
    cudaGetSymbolAddress((void**)&wlo, g_wlo);

    const int nx4 = (M_TOTAL * IN) / 4;
    const int nw4 = (GDIM * KDIM) / 4;
    split_kernel<<<(nx4 + 255) / 256, 256>>>(x, xhi, xlo, nx4);
    split_kernel<<<(nw4 + 255) / 256, 256>>>(W, whi, wlo, nw4);

    cudaFuncSetAttribute(gemm_tc_kernel,
                         cudaFuncAttributeMaxDynamicSharedMemorySize, SMEM_DYN);
    dim3 ggrid(GDIM / BN, M_TOTAL / BM);        // (12, 256)
    gemm_tc_kernel<<<ggrid, 256, SMEM_DYN>>>(bias);

    scan_p1_kernel<<<dim3(NCHUNK, BATCH), 512>>>(out);
    scan_p2_kernel<<<BATCH, 512>>>();
    scan_p3_kernel<<<(M_TOTAL * ODIM / 4) / 256, 256>>>(out);
}

// round 11
// speedup vs baseline: 4.1912x; 1.4430x over previous
#include <cuda_runtime.h>
#include <cuda_fp16.h>
#include <math.h>
#include <stdint.h>

#define BATCH 8
#define SEQ   4096
#define IN    256
#define GDIM  1536      // 2*OUT*3
#define KDIM  512       // WINDOW*IN
#define ODIM  512       // 2*OUT
#define M_TOTAL (BATCH*SEQ)   // 32768
#define NCHUNK 64
#define CLEN   64       // SEQ / NCHUNK

// ---- GEMM tiling ----
#define BM 128
#define BN 128
#define BK 32
#define NKT (KDIM / BK)        // 16 k-tiles
#define NSTAGE 3
// per-stage smem regions (bytes): A hi 8K | A lo 8K | B 8K
#define R_AHI 0
#define R_ALO 8192
#define R_B   16384
#define STAGE_BYTES 24576
#define SMEM_DYN (NSTAGE * STAGE_BYTES)

// ---- device scratch ----
__device__ float   g_act[(size_t)M_TOTAL * GDIM];            // 201MB activated gates
__device__ float   g_Q  [(size_t)M_TOTAL * ODIM];            // 67MB  so * prefix-product
__device__ __half  g_xhi[(size_t)M_TOTAL * IN];
__device__ __half  g_xlo[(size_t)M_TOTAL * IN];
__device__ __half  g_wh [(size_t)GDIM * KDIM];
__device__ float   g_A  [(size_t)BATCH * NCHUNK * ODIM];     // chunk f-product
__device__ float   g_B  [(size_t)BATCH * NCHUNK * ODIM];     // chunk local c end
__device__ float   g_C0 [(size_t)BATCH * NCHUNK * ODIM];     // chunk carry-in

// ---------------------------------------------------------------------------
// helpers
// ---------------------------------------------------------------------------
__device__ __forceinline__ uint32_t smem_u32(const void* p) {
    uint32_t a;
    asm("{ .reg .u64 t; cvta.to.shared.u64 t, %1; cvt.u32.u64 %0, t; }"
        : "=r"(a) : "l"(p));
    return a;
}

__device__ __forceinline__ void cp_async16(uint32_t dst, const void* src, int src_bytes) {
    asm volatile("cp.async.cg.shared.global [%0], [%1], 16, %2;"
                 :: "r"(dst), "l"(src), "r"(src_bytes));
}
__device__ __forceinline__ void cp_commit() {
    asm volatile("cp.async.commit_group;" ::: "memory");
}
template <int N>
__device__ __forceinline__ void cp_wait() {
    asm volatile("cp.async.wait_group %0;" :: "n"(N) : "memory");
}

__device__ __forceinline__ void ldsm_x4(unsigned* r, uint32_t addr) {
    asm volatile("ldmatrix.sync.aligned.m8n8.x4.shared.b16 {%0,%1,%2,%3}, [%4];"
                 : "=r"(r[0]), "=r"(r[1]), "=r"(r[2]), "=r"(r[3]) : "r"(addr));
}

__device__ __forceinline__ void mma16816h(float* d, const unsigned* a, const unsigned* b)
{
    asm volatile(
        "mma.sync.aligned.m16n8k16.row.col.f32.f16.f16.f32 "
        "{%0,%1,%2,%3}, {%4,%5,%6,%7}, {%8,%9}, {%0,%1,%2,%3};\n"
        : "+f"(d[0]), "+f"(d[1]), "+f"(d[2]), "+f"(d[3])
        : "r"(a[0]), "r"(a[1]), "r"(a[2]), "r"(a[3]), "r"(b[0]), "r"(b[1]));
}

__device__ __forceinline__ float fsigmoid(float t) {
    return __fdividef(1.f, 1.f + __expf(-t));
}
__device__ __forceinline__ float ftanh_fast(float t) {
    return __fmaf_rn(2.f, __fdividef(1.f, 1.f + __expf(-2.f * t)), -1.f);
}

// ---------------------------------------------------------------------------
// fp32 -> fp16 hi/lo split (x) ; fp32 -> fp16 round (W)
// ---------------------------------------------------------------------------
__global__ void split2_kernel(const float* __restrict__ src,
                              __half* __restrict__ hi,
                              __half* __restrict__ lo, int n4)
{
    int v = blockIdx.x * blockDim.x + threadIdx.x;
    if (v >= n4) return;
    float4 x = ((const float4*)src)[v];
    __half h0 = __float2half_rn(x.x), h1 = __float2half_rn(x.y);
    __half h2 = __float2half_rn(x.z), h3 = __float2half_rn(x.w);
    __half l0 = __float2half_rn(x.x - __half2float(h0));
    __half l1 = __float2half_rn(x.y - __half2float(h1));
    __half l2 = __float2half_rn(x.z - __half2float(h2));
    __half l3 = __float2half_rn(x.w - __half2float(h3));
    ushort4 hv = make_ushort4(__half_as_ushort(h0), __half_as_ushort(h1),
                              __half_as_ushort(h2), __half_as_ushort(h3));
    ushort4 lv = make_ushort4(__half_as_ushort(l0), __half_as_ushort(l1),
                              __half_as_ushort(l2), __half_as_ushort(l3));
    ((ushort4*)hi)[v] = hv;
    ((ushort4*)lo)[v] = lv;
}

__global__ void round_kernel(const float* __restrict__ src,
                             __half* __restrict__ dst, int n4)
{
    int v = blockIdx.x * blockDim.x + threadIdx.x;
    if (v >= n4) return;
    float4 x = ((const float4*)src)[v];
    ushort4 hv = make_ushort4(__half_as_ushort(__float2half_rn(x.x)),
                              __half_as_ushort(__float2half_rn(x.y)),
                              __half_as_ushort(__float2half_rn(x.z)),
                              __half_as_ushort(__float2half_rn(x.w)));
    ((ushort4*)dst)[v] = hv;
}

// ---------------------------------------------------------------------------
// Tensor-core GEMM (fp16 2-pass: A hi/lo exact split, B fp16 rounded),
// 3-stage cp.async pipeline, ldmatrix.x4 fragment loads.
// Block 128x128, K-tile 32, 256 threads = 8 warps (warp tile 64m x 32n).
// smem layout per tile row: 32 elems (64B) = 4 x 16B chunks, chunk q stored
// at q ^ ((row>>1)&3)  (same XOR-quarter swizzle as the verified R7 kernel).
// ---------------------------------------------------------------------------
__global__ __launch_bounds__(256)
void gemm_tc_kernel(const float* __restrict__ bias)
{
    extern __shared__ __align__(128) char dyn[];
    const uint32_t sbase = smem_u32(dyn);

    const int row0 = blockIdx.y * BM;
    const int col0 = blockIdx.x * BN;
    const int tid  = threadIdx.x;
    const int lane = tid & 31;
    const int w    = tid >> 5;
    const int wm   = (w & 1) * 64;     // warp m-offset
    const int wn   = (w >> 1) * 32;    // warp n-offset
    const int g    = lane >> 2;
    const int tig  = lane & 3;

    float acc[4][4][4];
    #pragma unroll
    for (int i = 0; i < 4; i++)
        #pragma unroll
        for (int j = 0; j < 4; j++)
            #pragma unroll
            for (int t = 0; t < 4; t++) acc[i][j][t] = 0.f;

    // ---- ldmatrix per-lane addressing ----
    // x4 = 4 m8n8 matrices: lanes 0-7 rows of mat0, 8-15 mat1, 16-23 mat2, 24-31 mat3.
    // mat0/1 = 16 tile-rows at col-chunk +0 ; mat2/3 = same rows at col-chunk +1.
    const int lr = lane & 15;          // row within 16-row tile
    const int lc = lane >> 4;          // col-chunk select (0/1)
    uint32_t a_off[4]; int a_sw[4];
    #pragma unroll
    for (int mi = 0; mi < 4; mi++) {
        int m = wm + mi * 16 + lr;
        a_off[mi] = (uint32_t)m * 64;
        a_sw[mi]  = (m >> 1) & 3;
    }
    uint32_t b_off[2]; int b_sw[2];
    #pragma unroll
    for (int np = 0; np < 2; np++) {
        int n = wn + np * 16 + lr;
        b_off[np] = (uint32_t)n * 64;
        b_sw[np]  = (n >> 1) & 3;
    }

    // ---- cp.async loader: per k-tile, 2 slots/thread ----
    const int l_m  = tid >> 2;
    const int l_qu = tid & 3;
    const int l_m2 = (tid + 256) >> 2;
    const int l_qu2 = (tid + 256) & 3;

    #define LOAD_STAGE(kt_, st_) do {                                         \
        const int  kg0     = (kt_) * BK;                                      \
        const bool shifted = (kg0 < IN);                                      \
        const int  kcol    = kg0 & (IN - 1);                                  \
        const uint32_t sb  = sbase + (st_) * STAGE_BYTES;                     \
        _Pragma("unroll")                                                     \
        for (int q = 0; q < 2; q++) {                                         \
            int m  = q ? l_m2 : l_m;                                          \
            int qu = q ? l_qu2 : l_qu;                                        \
            int qs = qu ^ ((m >> 1) & 3);                                     \
            /* A hi+lo */                                                     \
            int r  = row0 + m;                                                \
            int zb = (shifted && ((r & (SEQ - 1)) == 0)) ? 0 : 16;            \
            int rs = r - (shifted ? 1 : 0);                                   \
            if (!zb) rs = r;                                                  \
            size_t asrc = (size_t)rs * IN + kcol + qu * 8;                    \
            uint32_t adst = sb + R_AHI + m * 64 + qs * 16;                    \
            cp_async16(adst,        g_xhi + asrc, zb);                        \
            cp_async16(adst + 8192, g_xlo + asrc, zb);                        \
            /* B single fp16 */                                               \
            size_t bsrc = (size_t)(col0 + m) * KDIM + kg0 + qu * 8;           \
            cp_async16(sb + R_B + m * 64 + qs * 16, g_wh + bsrc, 16);         \
        }                                                                     \
    } while (0)

    // ---- prologue: prefetch k-tiles 0 and 1 ----
    LOAD_STAGE(0, 0); cp_commit();
    LOAD_STAGE(1, 1); cp_commit();

    int st = 0;
    for (int kt = 0; kt < NKT; kt++) {
        cp_wait<1>();
        __syncthreads();

        if (kt + 2 < NKT) {
            int st2 = st + 2; if (st2 >= NSTAGE) st2 -= NSTAGE;
            LOAD_STAGE(kt + 2, st2);
        }
        cp_commit();

        const uint32_t sb = sbase + st * STAGE_BYTES;

        #pragma unroll
        for (int j = 0; j < 2; j++) {
            const int kq = 2 * j + lc;     // 16B col-chunk for this lane
            unsigned ah[4][4], al[4][4], bb[4][2];
            #pragma unroll
            for (int mi = 0; mi < 4; mi++) {
                uint32_t ad = sb + R_AHI + a_off[mi] + (uint32_t)((kq ^ a_sw[mi]) << 4);
                ldsm_x4(ah[mi], ad);
                ldsm_x4(al[mi], ad + 8192);
            }
            #pragma unroll
            for (int np = 0; np < 2; np++) {
                unsigned t[4];
                uint32_t bd = sb + R_B + b_off[np] + (uint32_t)((kq ^ b_sw[np]) << 4);
                ldsm_x4(t, bd);
                bb[2 * np][0]     = t[0];
                bb[2 * np + 1][0] = t[1];
                bb[2 * np][1]     = t[2];
                bb[2 * np + 1][1] = t[3];
            }
            #pragma unroll
            for (int mi = 0; mi < 4; mi++)
                #pragma unroll
                for (int ni = 0; ni < 4; ni++) {
                    mma16816h(acc[mi][ni], ah[mi], bb[ni]);
                    mma16816h(acc[mi][ni], al[mi], bb[ni]);
                }
        }

        __syncthreads();
        st = st + 1; if (st >= NSTAGE) st = 0;
    }

    // ---- epilogue: bias + activation (block-uniform) + store ----
    const bool is_tanh = (col0 < 512);
    #pragma unroll
    for (int ni = 0; ni < 4; ni++) {
        int col = col0 + wn + ni * 8 + tig * 2;
        float b0 = bias[col], b1 = bias[col + 1];
        #pragma unroll
        for (int mi = 0; mi < 4; mi++) {
            int r0 = row0 + wm + mi * 16 + g;
            float v[4];
            v[0] = acc[mi][ni][0] + b0;
            v[1] = acc[mi][ni][1] + b1;
            v[2] = acc[mi][ni][2] + b0;
            v[3] = acc[mi][ni][3] + b1;
            #pragma unroll
            for (int t = 0; t < 4; t++)
                v[t] = is_tanh ? ftanh_fast(v[t]) : fsigmoid(v[t]);
            *(float2*)&g_act[(size_t)r0 * GDIM + col]       = make_float2(v[0], v[1]);
            *(float2*)&g_act[(size_t)(r0 + 8) * GDIM + col] = make_float2(v[2], v[3]);
        }
    }
}

// ---------------------------------------------------------------------------
// Scan phase 1: chunk-local scan.  c_local with c0=0, P = inclusive prod(f).
// ---------------------------------------------------------------------------
__global__ __launch_bounds__(512)
void scan_p1_kernel(float* __restrict__ out)
{
    const int ch = threadIdx.x;
    const int d  = ch >> 8;
    const int k  = blockIdx.x;
    const int b  = blockIdx.y;

    const int s0  = (k << 6) + (d ? (CLEN - 1) : 0);
    const int stp = d ? -1 : 1;
    const float* gp = g_act + (size_t)(b * SEQ + s0) * GDIM;
    float* op = out + (size_t)(b * SEQ + s0) * ODIM + ch;
    float* qp = g_Q + (size_t)(b * SEQ + s0) * ODIM + ch;
    const ptrdiff_t gst = (ptrdiff_t)stp * GDIM;
    const ptrdiff_t ost = (ptrdiff_t)stp * ODIM;

    float c = 0.f, P = 1.f;
    #pragma unroll 4
    for (int i = 0; i < CLEN; i++) {
        float z  = gp[ch];
        float f  = gp[512 + ch];
        float so = gp[1024 + ch];
        c = __fmaf_rn(f, c, __fmaf_rn(-f, z, z));
        P *= f;
        *op = so * c;
        *qp = so * P;
        gp += gst; op += ost; qp += ost;
    }
    size_t idx = (size_t)((b << 6) + k) * ODIM + ch;
    g_A[idx] = P;
    g_B[idx] = c;
}

// ---------------------------------------------------------------------------
// Scan phase 2: scan over chunk boundaries, stores carry-in.
// ---------------------------------------------------------------------------
__global__ __launch_bounds__(512)
void scan_p2_kernel()
{
    const int ch = threadIdx.x;
    const int d  = ch >> 8;
    const int b  = blockIdx.x;
    float c0 = 0.f;
    if (d == 0) {
        for (int k = 0; k < NCHUNK; k++) {
            size_t idx = (size_t)((b << 6) + k) * ODIM + ch;
            g_C0[idx] = c0;
            c0 = __fmaf_rn(g_A[idx], c0, g_B[idx]);
        }
    } else {
        for (int k = NCHUNK - 1; k >= 0; k--) {
            size_t idx = (size_t)((b << 6) + k) * ODIM + ch;
            g_C0[idx] = c0;
            c0 = __fmaf_rn(g_A[idx], c0, g_B[idx]);
        }
    }
}

// ---------------------------------------------------------------------------
// Scan phase 3: out += Q * carry_in(chunk).
// ---------------------------------------------------------------------------
__global__ __launch_bounds__(256)
void scan_p3_kernel(float* __restrict__ out)
{
    const int v   = blockIdx.x * 256 + threadIdx.x;   // float4 index
    const int row = v >> 7;
    const int c4  = (v & 127) << 2;
    const int b   = row >> 12;
    const int s   = row & (SEQ - 1);
    const int k   = s >> 6;

    float4 q  = ((const float4*)g_Q)[v];
    float4 c0 = *(const float4*)&g_C0[(size_t)((b << 6) + k) * ODIM + c4];
    float4 o  = ((const float4*)out)[v];
    o.x = __fmaf_rn(q.x, c0.x, o.x);
    o.y = __fmaf_rn(q.y, c0.y, o.y);
    o.z = __fmaf_rn(q.z, c0.z, o.z);
    o.w = __fmaf_rn(q.w, c0.w, o.w);
    ((float4*)out)[v] = o;
}

extern "C" void kernel_launch(void* const* d_in, const int* in_sizes, int n_in,
                              void* d_out, int out_size)
{
    const float* x    = (const float*)d_in[0];  // (8, 4096, 256)
    const float* W    = (const float*)d_in[1];  // (1536, 512)
    const float* bias = (const float*)d_in[2];  // (1536,)
    float* out = (float*)d_out;                 // (8, 4096, 512)

    __half *xhi, *xlo, *wh;
    cudaGetSymbolAddress((void**)&xhi, g_xhi);
    cudaGetSymbolAddress((void**)&xlo, g_xlo);
    cudaGetSymbolAddress((void**)&wh,  g_wh);

    const int nx4 = (M_TOTAL * IN) / 4;
    const int nw4 = (GDIM * KDIM) / 4;
    split2_kernel<<<(nx4 + 255) / 256, 256>>>(x, xhi, xlo, nx4);
    round_kernel<<<(nw4 + 255) / 256, 256>>>(W, wh, nw4);

    cudaFuncSetAttribute(gemm_tc_kernel,
                         cudaFuncAttributeMaxDynamicSharedMemorySize, SMEM_DYN);
    dim3 ggrid(GDIM / BN, M_TOTAL / BM);        // (12, 256)
    gemm_tc_kernel<<<ggrid, 256, SMEM_DYN>>>(bias);

    scan_p1_kernel<<<dim3(NCHUNK, BATCH), 512>>>(out);
    scan_p2_kernel<<<BATCH, 512>>>();
    scan_p3_kernel<<<(M_TOTAL * ODIM / 4) / 256, 256>>>(out);
}

// round 12
// speedup vs baseline: 5.6974x; 1.3594x over previous
#include <cuda_runtime.h>
#include <cuda_fp16.h>
#include <math.h>
#include <stdint.h>

#define BATCH 8
#define SEQ   4096
#define IN    256
#define GDIM  1536      // 2*OUT*3
#define KDIM  512       // WINDOW*IN
#define ODIM  512       // 2*OUT
#define M_TOTAL (BATCH*SEQ)   // 32768
#define NCHUNK 64
#define CLEN   64       // SEQ / NCHUNK

// ---- GEMM tiling ----
#define BM 128
#define BN 128
#define BK 32
#define NKT (KDIM / BK)        // 16 k-tiles
#define NSTAGE 4
// per-stage smem regions (bytes): A 8K | B 8K
#define R_A 0
#define R_B 8192
#define STAGE_BYTES 16384
#define SMEM_DYN (NSTAGE * STAGE_BYTES)

// ---- device scratch ----
__device__ float   g_act[(size_t)M_TOTAL * GDIM];            // 201MB activated gates
__device__ float   g_Q  [(size_t)M_TOTAL * ODIM];            // 67MB  so * prefix-product
__device__ __half  g_xh [(size_t)M_TOTAL * IN];
__device__ __half  g_wh [(size_t)GDIM * KDIM];
__device__ float   g_A  [(size_t)BATCH * NCHUNK * ODIM];     // chunk f-product
__device__ float   g_B  [(size_t)BATCH * NCHUNK * ODIM];     // chunk local c end
__device__ float   g_C0 [(size_t)BATCH * NCHUNK * ODIM];     // chunk carry-in

// ---------------------------------------------------------------------------
// helpers
// ---------------------------------------------------------------------------
__device__ __forceinline__ uint32_t smem_u32(const void* p) {
    uint32_t a;
    asm("{ .reg .u64 t; cvta.to.shared.u64 t, %1; cvt.u32.u64 %0, t; }"
        : "=r"(a) : "l"(p));
    return a;
}

__device__ __forceinline__ void cp_async16(uint32_t dst, const void* src, int src_bytes) {
    asm volatile("cp.async.cg.shared.global [%0], [%1], 16, %2;"
                 :: "r"(dst), "l"(src), "r"(src_bytes));
}
__device__ __forceinline__ void cp_commit() {
    asm volatile("cp.async.commit_group;" ::: "memory");
}
template <int N>
__device__ __forceinline__ void cp_wait() {
    asm volatile("cp.async.wait_group %0;" :: "n"(N) : "memory");
}

__device__ __forceinline__ void ldsm_x4(unsigned* r, uint32_t addr) {
    asm volatile("ldmatrix.sync.aligned.m8n8.x4.shared.b16 {%0,%1,%2,%3}, [%4];"
                 : "=r"(r[0]), "=r"(r[1]), "=r"(r[2]), "=r"(r[3]) : "r"(addr));
}

__device__ __forceinline__ void mma16816h(float* d, const unsigned* a, const unsigned* b)
{
    asm volatile(
        "mma.sync.aligned.m16n8k16.row.col.f32.f16.f16.f32 "
        "{%0,%1,%2,%3}, {%4,%5,%6,%7}, {%8,%9}, {%0,%1,%2,%3};\n"
        : "+f"(d[0]), "+f"(d[1]), "+f"(d[2]), "+f"(d[3])
        : "r"(a[0]), "r"(a[1]), "r"(a[2]), "r"(a[3]), "r"(b[0]), "r"(b[1]));
}

__device__ __forceinline__ float fsigmoid(float t) {
    return __fdividef(1.f, 1.f + __expf(-t));
}
__device__ __forceinline__ float ftanh_fast(float t) {
    return __fmaf_rn(2.f, __fdividef(1.f, 1.f + __expf(-2.f * t)), -1.f);
}

// ---------------------------------------------------------------------------
// fp32 -> fp16 round
// ---------------------------------------------------------------------------
__global__ void round_kernel(const float* __restrict__ src,
                             __half* __restrict__ dst, int n4)
{
    int v = blockIdx.x * blockDim.x + threadIdx.x;
    if (v >= n4) return;
    float4 x = ((const float4*)src)[v];
    ushort4 hv = make_ushort4(__half_as_ushort(__float2half_rn(x.x)),
                              __half_as_ushort(__float2half_rn(x.y)),
                              __half_as_ushort(__float2half_rn(x.z)),
                              __half_as_ushort(__float2half_rn(x.w)));
    ((ushort4*)dst)[v] = hv;
}

// ---------------------------------------------------------------------------
// Tensor-core GEMM (single-pass fp16, f32 accum), 4-stage cp.async pipeline,
// ldmatrix.x4 fragment loads.
// Block 128x128, K-tile 32, 256 threads = 8 warps (warp tile 64m x 32n).
// smem layout per tile row: 32 elems (64B) = 4 x 16B chunks, chunk q stored
// at q ^ ((row>>1)&3)  (same XOR-quarter swizzle as the verified R7 kernel).
// ---------------------------------------------------------------------------
__global__ __launch_bounds__(256)
void gemm_tc_kernel(const float* __restrict__ bias)
{
    extern __shared__ __align__(128) char dyn[];
    const uint32_t sbase = smem_u32(dyn);

    const int row0 = blockIdx.y * BM;
    const int col0 = blockIdx.x * BN;
    const int tid  = threadIdx.x;
    const int lane = tid & 31;
    const int w    = tid >> 5;
    const int wm   = (w & 1) * 64;     // warp m-offset
    const int wn   = (w >> 1) * 32;    // warp n-offset
    const int g    = lane >> 2;
    const int tig  = lane & 3;

    float acc[4][4][4];
    #pragma unroll
    for (int i = 0; i < 4; i++)
        #pragma unroll
        for (int j = 0; j < 4; j++)
            #pragma unroll
            for (int t = 0; t < 4; t++) acc[i][j][t] = 0.f;

    // ---- ldmatrix per-lane addressing ----
    const int lr = lane & 15;          // row within 16-row tile
    const int lc = lane >> 4;          // col-chunk select (0/1)
    uint32_t a_off[4]; int a_sw[4];
    #pragma unroll
    for (int mi = 0; mi < 4; mi++) {
        int m = wm + mi * 16 + lr;
        a_off[mi] = (uint32_t)m * 64;
        a_sw[mi]  = (m >> 1) & 3;
    }
    uint32_t b_off[2]; int b_sw[2];
    #pragma unroll
    for (int np = 0; np < 2; np++) {
        int n = wn + np * 16 + lr;
        b_off[np] = (uint32_t)n * 64;
        b_sw[np]  = (n >> 1) & 3;
    }

    // ---- cp.async loader: per k-tile, 2 slots/thread ----
    const int l_m  = tid >> 2;
    const int l_qu = tid & 3;
    const int l_m2 = (tid + 256) >> 2;
    const int l_qu2 = (tid + 256) & 3;

    #define LOAD_STAGE(kt_, st_) do {                                         \
        const int  kg0     = (kt_) * BK;                                      \
        const bool shifted = (kg0 < IN);                                      \
        const int  kcol    = kg0 & (IN - 1);                                  \
        const uint32_t sb  = sbase + (st_) * STAGE_BYTES;                     \
        _Pragma("unroll")                                                     \
        for (int q = 0; q < 2; q++) {                                         \
            int m  = q ? l_m2 : l_m;                                          \
            int qu = q ? l_qu2 : l_qu;                                        \
            int qs = qu ^ ((m >> 1) & 3);                                     \
            /* A */                                                           \
            int r  = row0 + m;                                                \
            int zb = (shifted && ((r & (SEQ - 1)) == 0)) ? 0 : 16;            \
            int rs = r - (shifted ? 1 : 0);                                   \
            if (!zb) rs = r;                                                  \
            size_t asrc = (size_t)rs * IN + kcol + qu * 8;                    \
            cp_async16(sb + R_A + m * 64 + qs * 16, g_xh + asrc, zb);         \
            /* B */                                                           \
            size_t bsrc = (size_t)(col0 + m) * KDIM + kg0 + qu * 8;           \
            cp_async16(sb + R_B + m * 64 + qs * 16, g_wh + bsrc, 16);         \
        }                                                                     \
    } while (0)

    // ---- prologue: prefetch k-tiles 0..2 ----
    LOAD_STAGE(0, 0); cp_commit();
    LOAD_STAGE(1, 1); cp_commit();
    LOAD_STAGE(2, 2); cp_commit();

    int st = 0;
    for (int kt = 0; kt < NKT; kt++) {
        cp_wait<2>();              // tile kt complete (kt+1, kt+2 may be in flight)
        __syncthreads();

        if (kt + 3 < NKT) {
            int st2 = st + 3; if (st2 >= NSTAGE) st2 -= NSTAGE;
            LOAD_STAGE(kt + 3, st2);
        }
        cp_commit();

        const uint32_t sb = sbase + st * STAGE_BYTES;

        #pragma unroll
        for (int j = 0; j < 2; j++) {
            const int kq = 2 * j + lc;     // 16B col-chunk for this lane
            unsigned ah[4][4], bb[4][2];
            #pragma unroll
            for (int mi = 0; mi < 4; mi++) {
                uint32_t ad = sb + R_A + a_off[mi] + (uint32_t)((kq ^ a_sw[mi]) << 4);
                ldsm_x4(ah[mi], ad);
            }
            #pragma unroll
            for (int np = 0; np < 2; np++) {
                unsigned t[4];
                uint32_t bd = sb + R_B + b_off[np] + (uint32_t)((kq ^ b_sw[np]) << 4);
                ldsm_x4(t, bd);
                bb[2 * np][0]     = t[0];
                bb[2 * np + 1][0] = t[1];
                bb[2 * np][1]     = t[2];
                bb[2 * np + 1][1] = t[3];
            }
            #pragma unroll
            for (int mi = 0; mi < 4; mi++)
                #pragma unroll
                for (int ni = 0; ni < 4; ni++)
                    mma16816h(acc[mi][ni], ah[mi], bb[ni]);
        }

        __syncthreads();
        st = st + 1; if (st >= NSTAGE) st = 0;
    }

    // ---- epilogue: bias + activation (block-uniform) + store ----
    const bool is_tanh = (col0 < 512);
    #pragma unroll
    for (int ni = 0; ni < 4; ni++) {
        int col = col0 + wn + ni * 8 + tig * 2;
        float b0 = bias[col], b1 = bias[col + 1];
        #pragma unroll
        for (int mi = 0; mi < 4; mi++) {
            int r0 = row0 + wm + mi * 16 + g;
            float v[4];
            v[0] = acc[mi][ni][0] + b0;
            v[1] = acc[mi][ni][1] + b1;
            v[2] = acc[mi][ni][2] + b0;
            v[3] = acc[mi][ni][3] + b1;
            #pragma unroll
            for (int t = 0; t < 4; t++)
                v[t] = is_tanh ? ftanh_fast(v[t]) : fsigmoid(v[t]);
            *(float2*)&g_act[(size_t)r0 * GDIM + col]       = make_float2(v[0], v[1]);
            *(float2*)&g_act[(size_t)(r0 + 8) * GDIM + col] = make_float2(v[2], v[3]);
        }
    }
}

// ---------------------------------------------------------------------------
// Scan phase 1: chunk-local scan.  c_local with c0=0, P = inclusive prod(f).
// ---------------------------------------------------------------------------
__global__ __launch_bounds__(512)
void scan_p1_kernel(float* __restrict__ out)
{
    const int ch = threadIdx.x;
    const int d  = ch >> 8;
    const int k  = blockIdx.x;
    const int b  = blockIdx.y;

    const int s0  = (k << 6) + (d ? (CLEN - 1) : 0);
    const int stp = d ? -1 : 1;
    const float* gp = g_act + (size_t)(b * SEQ + s0) * GDIM;
    float* op = out + (size_t)(b * SEQ + s0) * ODIM + ch;
    float* qp = g_Q + (size_t)(b * SEQ + s0) * ODIM + ch;
    const ptrdiff_t gst = (ptrdiff_t)stp * GDIM;
    const ptrdiff_t ost = (ptrdiff_t)stp * ODIM;

    float c = 0.f, P = 1.f;
    #pragma unroll 4
    for (int i = 0; i < CLEN; i++) {
        float z  = gp[ch];
        float f  = gp[512 + ch];
        float so = gp[1024 + ch];
        c = __fmaf_rn(f, c, __fmaf_rn(-f, z, z));
        P *= f;
        *op = so * c;
        *qp = so * P;
        gp += gst; op += ost; qp += ost;
    }
    size_t idx = (size_t)((b << 6) + k) * ODIM + ch;
    g_A[idx] = P;
    g_B[idx] = c;
}

// ---------------------------------------------------------------------------
// Scan phase 2: scan over chunk boundaries, stores carry-in.
// ---------------------------------------------------------------------------
__global__ __launch_bounds__(512)
void scan_p2_kernel()
{
    const int ch = threadIdx.x;
    const int d  = ch >> 8;
    const int b  = blockIdx.x;
    float c0 = 0.f;
    if (d == 0) {
        for (int k = 0; k < NCHUNK; k++) {
            size_t idx = (size_t)((b << 6) + k) * ODIM + ch;
            g_C0[idx] = c0;
            c0 = __fmaf_rn(g_A[idx], c0, g_B[idx]);
        }
    } else {
        for (int k = NCHUNK - 1; k >= 0; k--) {
            size_t idx = (size_t)((b << 6) + k) * ODIM + ch;
            g_C0[idx] = c0;
            c0 = __fmaf_rn(g_A[idx], c0, g_B[idx]);
        }
    }
}

// ---------------------------------------------------------------------------
// Scan phase 3: out += Q * carry_in(chunk).
// ---------------------------------------------------------------------------
__global__ __launch_bounds__(256)
void scan_p3_kernel(float* __restrict__ out)
{
    const int v   = blockIdx.x * 256 + threadIdx.x;   // float4 index
    const int row = v >> 7;
    const int c4  = (v & 127) << 2;
    const int b   = row >> 12;
    const int s   = row & (SEQ - 1);
    const int k   = s >> 6;

    float4 q  = ((const float4*)g_Q)[v];
    float4 c0 = *(const float4*)&g_C0[(size_t)((b << 6) + k) * ODIM + c4];
    float4 o  = ((const float4*)out)[v];
    o.x = __fmaf_rn(q.x, c0.x, o.x);
    o.y = __fmaf_rn(q.y, c0.y, o.y);
    o.z = __fmaf_rn(q.z, c0.z, o.z);
    o.w = __fmaf_rn(q.w, c0.w, o.w);
    ((float4*)out)[v] = o;
}

extern "C" void kernel_launch(void* const* d_in, const int* in_sizes, int n_in,
                              void* d_out, int out_size)
{
    const float* x    = (const float*)d_in[0];  // (8, 4096, 256)
    const float* W    = (const float*)d_in[1];  // (1536, 512)
    const float* bias = (const float*)d_in[2];  // (1536,)
    float* out = (float*)d_out;                 // (8, 4096, 512)

    __half *xh, *wh;
    cudaGetSymbolAddress((void**)&xh, g_xh);
    cudaGetSymbolAddress((void**)&wh, g_wh);

    const int nx4 = (M_TOTAL * IN) / 4;
    const int nw4 = (GDIM * KDIM) / 4;
    round_kernel<<<(nx4 + 255) / 256, 256>>>(x, xh, nx4);
    round_kernel<<<(nw4 + 255) / 256, 256>>>(W, wh, nw4);

    cudaFuncSetAttribute(gemm_tc_kernel,
                         cudaFuncAttributeMaxDynamicSharedMemorySize, SMEM_DYN);
    dim3 ggrid(GDIM / BN, M_TOTAL / BM);        // (12, 256)
    gemm_tc_kernel<<<ggrid, 256, SMEM_DYN>>>(bias);

    scan_p1_kernel<<<dim3(NCHUNK, BATCH), 512>>>(out);
    scan_p2_kernel<<<BATCH, 512>>>();
    scan_p3_kernel<<<(M_TOTAL * ODIM / 4) / 256, 256>>>(out);
}

// round 13
// speedup vs baseline: 6.2716x; 1.1008x over previous
#include <cuda_runtime.h>
#include <cuda_fp16.h>
#include <math.h>
#include <stdint.h>

#define BATCH 8
#define SEQ   4096
#define IN    256
#define GDIM  1536      // 2*OUT*3
#define KDIM  512       // WINDOW*IN
#define ODIM  512       // 2*OUT
#define M_TOTAL (BATCH*SEQ)   // 32768
#define NCHUNK 64
#define CLEN   64       // SEQ / NCHUNK

// ---- GEMM tiling ----
#define BM 128
#define BN 128
#define BK 32
#define NKT (KDIM / BK)        // 16 k-tiles
#define NSTAGE 4
// per-stage smem regions (bytes): A 8K | B 8K
#define R_A 0
#define R_B 8192
#define STAGE_BYTES 16384
#define SMEM_DYN (NSTAGE * STAGE_BYTES)

// ---- device scratch ----
__device__ float   g_act[(size_t)M_TOTAL * GDIM];            // 201MB activated gates
__device__ __half  g_xh [(size_t)M_TOTAL * IN];
__device__ __half  g_wh [(size_t)GDIM * KDIM];
__device__ float   g_A  [(size_t)BATCH * NCHUNK * ODIM];     // chunk f-product
__device__ float   g_B  [(size_t)BATCH * NCHUNK * ODIM];     // chunk local c end
__device__ float   g_C0 [(size_t)BATCH * NCHUNK * ODIM];     // chunk carry-in

// ---------------------------------------------------------------------------
// helpers
// ---------------------------------------------------------------------------
__device__ __forceinline__ uint32_t smem_u32(const void* p) {
    uint32_t a;
    asm("{ .reg .u64 t; cvta.to.shared.u64 t, %1; cvt.u32.u64 %0, t; }"
        : "=r"(a) : "l"(p));
    return a;
}

__device__ __forceinline__ void cp_async16(uint32_t dst, const void* src, int src_bytes) {
    asm volatile("cp.async.cg.shared.global [%0], [%1], 16, %2;"
                 :: "r"(dst), "l"(src), "r"(src_bytes));
}
__device__ __forceinline__ void cp_commit() {
    asm volatile("cp.async.commit_group;" ::: "memory");
}
template <int N>
__device__ __forceinline__ void cp_wait() {
    asm volatile("cp.async.wait_group %0;" :: "n"(N) : "memory");
}

__device__ __forceinline__ void ldsm_x4(unsigned* r, uint32_t addr) {
    asm volatile("ldmatrix.sync.aligned.m8n8.x4.shared.b16 {%0,%1,%2,%3}, [%4];"
                 : "=r"(r[0]), "=r"(r[1]), "=r"(r[2]), "=r"(r[3]) : "r"(addr));
}

__device__ __forceinline__ void mma16816h(float* d, const unsigned* a, const unsigned* b)
{
    asm volatile(
        "mma.sync.aligned.m16n8k16.row.col.f32.f16.f16.f32 "
        "{%0,%1,%2,%3}, {%4,%5,%6,%7}, {%8,%9}, {%0,%1,%2,%3};\n"
        : "+f"(d[0]), "+f"(d[1]), "+f"(d[2]), "+f"(d[3])
        : "r"(a[0]), "r"(a[1]), "r"(a[2]), "r"(a[3]), "r"(b[0]), "r"(b[1]));
}

__device__ __forceinline__ float fsigmoid(float t) {
    return __fdividef(1.f, 1.f + __expf(-t));
}
__device__ __forceinline__ float ftanh_fast(float t) {
    return __fmaf_rn(2.f, __fdividef(1.f, 1.f + __expf(-2.f * t)), -1.f);
}

// ---------------------------------------------------------------------------
// fp32 -> fp16 round
// ---------------------------------------------------------------------------
__global__ void round_kernel(const float* __restrict__ src,
                             __half* __restrict__ dst, int n4)
{
    int v = blockIdx.x * blockDim.x + threadIdx.x;
    if (v >= n4) return;
    float4 x = ((const float4*)src)[v];
    ushort4 hv = make_ushort4(__half_as_ushort(__float2half_rn(x.x)),
                              __half_as_ushort(__float2half_rn(x.y)),
                              __half_as_ushort(__float2half_rn(x.z)),
                              __half_as_ushort(__float2half_rn(x.w)));
    ((ushort4*)dst)[v] = hv;
}

// ---------------------------------------------------------------------------
// Tensor-core GEMM (single-pass fp16, f32 accum), 4-stage cp.async pipeline.
// Block 128x128, K-tile 32, 128 threads = 4 warps, warp tile 64m x 64n.
// smem layout per tile row: 32 elems (64B) = 4 x 16B chunks, chunk q stored
// at q ^ ((row>>1)&3)  (verified XOR-quarter swizzle).
// ---------------------------------------------------------------------------
__global__ __launch_bounds__(128)
void gemm_tc_kernel(const float* __restrict__ bias)
{
    extern __shared__ __align__(128) char dyn[];
    const uint32_t sbase = smem_u32(dyn);

    const int row0 = blockIdx.y * BM;
    const int col0 = blockIdx.x * BN;
    const int tid  = threadIdx.x;
    const int lane = tid & 31;
    const int w    = tid >> 5;
    const int wm   = (w & 1) * 64;     // warp m-offset
    const int wn   = (w >> 1) * 64;    // warp n-offset
    const int g    = lane >> 2;
    const int tig  = lane & 3;

    float acc[4][8][4];
    #pragma unroll
    for (int i = 0; i < 4; i++)
        #pragma unroll
        for (int j = 0; j < 8; j++)
            #pragma unroll
            for (int t = 0; t < 4; t++) acc[i][j][t] = 0.f;

    // ---- ldmatrix per-lane addressing ----
    const int lr = lane & 15;          // row within 16-row tile
    const int lc = lane >> 4;          // col-chunk select (0/1)
    uint32_t a_off[4]; int a_sw[4];
    #pragma unroll
    for (int mi = 0; mi < 4; mi++) {
        int m = wm + mi * 16 + lr;
        a_off[mi] = (uint32_t)m * 64;
        a_sw[mi]  = (m >> 1) & 3;
    }
    uint32_t b_off[4]; int b_sw[4];
    #pragma unroll
    for (int np = 0; np < 4; np++) {
        int n = wn + np * 16 + lr;
        b_off[np] = (uint32_t)n * 64;
        b_sw[np]  = (n >> 1) & 3;
    }

    // ---- cp.async loader: per k-tile, 4 slots/thread (A + B each) ----
    #define LOAD_STAGE(kt_, st_) do {                                         \
        const int  kg0     = (kt_) * BK;                                      \
        const bool shifted = (kg0 < IN);                                      \
        const int  kcol    = kg0 & (IN - 1);                                  \
        const uint32_t sb  = sbase + (st_) * STAGE_BYTES;                     \
        _Pragma("unroll")                                                     \
        for (int q = 0; q < 4; q++) {                                         \
            int slot = tid + q * 128;                                         \
            int m  = slot >> 2;                                               \
            int qu = slot & 3;                                                \
            int qs = qu ^ ((m >> 1) & 3);                                     \
            /* A */                                                           \
            int r  = row0 + m;                                                \
            int zb = (shifted && ((r & (SEQ - 1)) == 0)) ? 0 : 16;            \
            int rs = r - (shifted ? 1 : 0);                                   \
            if (!zb) rs = r;                                                  \
            size_t asrc = (size_t)rs * IN + kcol + qu * 8;                    \
            cp_async16(sb + R_A + m * 64 + qs * 16, g_xh + asrc, zb);         \
            /* B */                                                           \
            size_t bsrc = (size_t)(col0 + m) * KDIM + kg0 + qu * 8;           \
            cp_async16(sb + R_B + m * 64 + qs * 16, g_wh + bsrc, 16);         \
        }                                                                     \
    } while (0)

    // ---- prologue: prefetch k-tiles 0..2 ----
    LOAD_STAGE(0, 0); cp_commit();
    LOAD_STAGE(1, 1); cp_commit();
    LOAD_STAGE(2, 2); cp_commit();

    int st = 0;
    for (int kt = 0; kt < NKT; kt++) {
        cp_wait<2>();              // tile kt complete (kt+1, kt+2 may be in flight)
        __syncthreads();

        if (kt + 3 < NKT) {
            int st2 = st + 3; if (st2 >= NSTAGE) st2 -= NSTAGE;
            LOAD_STAGE(kt + 3, st2);
        }
        cp_commit();

        const uint32_t sb = sbase + st * STAGE_BYTES;

        #pragma unroll
        for (int j = 0; j < 2; j++) {
            const int kq = 2 * j + lc;     // 16B col-chunk for this lane
            unsigned ah[4][4], bb[8][2];
            #pragma unroll
            for (int mi = 0; mi < 4; mi++) {
                uint32_t ad = sb + R_A + a_off[mi] + (uint32_t)((kq ^ a_sw[mi]) << 4);
                ldsm_x4(ah[mi], ad);
            }
            #pragma unroll
            for (int np = 0; np < 4; np++) {
                unsigned t[4];
                uint32_t bd = sb + R_B + b_off[np] + (uint32_t)((kq ^ b_sw[np]) << 4);
                ldsm_x4(t, bd);
                bb[2 * np][0]     = t[0];
                bb[2 * np + 1][0] = t[1];
                bb[2 * np][1]     = t[2];
                bb[2 * np + 1][1] = t[3];
            }
            #pragma unroll
            for (int mi = 0; mi < 4; mi++)
                #pragma unroll
                for (int ni = 0; ni < 8; ni++)
                    mma16816h(acc[mi][ni], ah[mi], bb[ni]);
        }

        __syncthreads();
        st = st + 1; if (st >= NSTAGE) st = 0;
    }

    // ---- epilogue: bias + activation (block-uniform) + store ----
    const bool is_tanh = (col0 < 512);
    #pragma unroll
    for (int ni = 0; ni < 8; ni++) {
        int col = col0 + wn + ni * 8 + tig * 2;
        float b0 = bias[col], b1 = bias[col + 1];
        #pragma unroll
        for (int mi = 0; mi < 4; mi++) {
            int r0 = row0 + wm + mi * 16 + g;
            float v[4];
            v[0] = acc[mi][ni][0] + b0;
            v[1] = acc[mi][ni][1] + b1;
            v[2] = acc[mi][ni][2] + b0;
            v[3] = acc[mi][ni][3] + b1;
            #pragma unroll
            for (int t = 0; t < 4; t++)
                v[t] = is_tanh ? ftanh_fast(v[t]) : fsigmoid(v[t]);
            *(float2*)&g_act[(size_t)r0 * GDIM + col]       = make_float2(v[0], v[1]);
            *(float2*)&g_act[(size_t)(r0 + 8) * GDIM + col] = make_float2(v[2], v[3]);
        }
    }
}

// ---------------------------------------------------------------------------
// Scan phase 1a: chunk summary only.  P = prod(f), c_end (local scan, c0=0).
// Reads z,f only (no so) -> 134MB.
// ---------------------------------------------------------------------------
__global__ __launch_bounds__(512)
void scan_p1a_kernel()
{
    const int ch = threadIdx.x;
    const int d  = ch >> 8;
    const int k  = blockIdx.x;
    const int b  = blockIdx.y;

    const int s0  = (k << 6) + (d ? (CLEN - 1) : 0);
    const int stp = d ? -1 : 1;
    const float* gp = g_act + (size_t)(b * SEQ + s0) * GDIM;
    const ptrdiff_t gst = (ptrdiff_t)stp * GDIM;

    float c = 0.f, P = 1.f;
    #pragma unroll 4
    for (int i = 0; i < CLEN; i++) {
        float z = gp[ch];
        float f = gp[512 + ch];
        c = __fmaf_rn(f, c, __fmaf_rn(-f, z, z));
        P *= f;
        gp += gst;
    }
    size_t idx = (size_t)((b << 6) + k) * ODIM + ch;
    g_A[idx] = P;
    g_B[idx] = c;
}

// ---------------------------------------------------------------------------
// Scan phase 2: scan over chunk boundaries, stores carry-in per chunk.
// ---------------------------------------------------------------------------
__global__ __launch_bounds__(512)
void scan_p2_kernel()
{
    const int ch = threadIdx.x;
    const int d  = ch >> 8;
    const int b  = blockIdx.x;
    float c0 = 0.f;
    if (d == 0) {
        for (int k = 0; k < NCHUNK; k++) {
            size_t idx = (size_t)((b << 6) + k) * ODIM + ch;
            g_C0[idx] = c0;
            c0 = __fmaf_rn(g_A[idx], c0, g_B[idx]);
        }
    } else {
        for (int k = NCHUNK - 1; k >= 0; k--) {
            size_t idx = (size_t)((b << 6) + k) * ODIM + ch;
            g_C0[idx] = c0;
            c0 = __fmaf_rn(g_A[idx], c0, g_B[idx]);
        }
    }
}

// ---------------------------------------------------------------------------
// Scan phase 1b: final scan with carry-in, writes out directly.
// ---------------------------------------------------------------------------
__global__ __launch_bounds__(512)
void scan_p1b_kernel(float* __restrict__ out)
{
    const int ch = threadIdx.x;
    const int d  = ch >> 8;
    const int k  = blockIdx.x;
    const int b  = blockIdx.y;

    const int s0  = (k << 6) + (d ? (CLEN - 1) : 0);
    const int stp = d ? -1 : 1;
    const float* gp = g_act + (size_t)(b * SEQ + s0) * GDIM;
    float* op = out + (size_t)(b * SEQ + s0) * ODIM + ch;
    const ptrdiff_t gst = (ptrdiff_t)stp * GDIM;
    const ptrdiff_t ost = (ptrdiff_t)stp * ODIM;

    float c = g_C0[(size_t)((b << 6) + k) * ODIM + ch];
    #pragma unroll 4
    for (int i = 0; i < CLEN; i++) {
        float z  = gp[ch];
        float f  = gp[512 + ch];
        float so = gp[1024 + ch];
        c = __fmaf_rn(f, c, __fmaf_rn(-f, z, z));
        *op = so * c;
        gp += gst; op += ost;
    }
}

extern "C" void kernel_launch(void* const* d_in, const int* in_sizes, int n_in,
                              void* d_out, int out_size)
{
    const float* x    = (const float*)d_in[0];  // (8, 4096, 256)
    const float* W    = (const float*)d_in[1];  // (1536, 512)
    const float* bias = (const float*)d_in[2];  // (1536,)
    float* out = (float*)d_out;                 // (8, 4096, 512)

    __half *xh, *wh;
    cudaGetSymbolAddress((void**)&xh, g_xh);
    cudaGetSymbolAddress((void**)&wh, g_wh);

    const int nx4 = (M_TOTAL * IN) / 4;
    const int nw4 = (GDIM * KDIM) / 4;
    round_kernel<<<(nx4 + 255) / 256, 256>>>(x, xh, nx4);
    round_kernel<<<(nw4 + 255) / 256, 256>>>(W, wh, nw4);

    cudaFuncSetAttribute(gemm_tc_kernel,
                         cudaFuncAttributeMaxDynamicSharedMemorySize, SMEM_DYN);
    dim3 ggrid(GDIM / BN, M_TOTAL / BM);        // (12, 256)
    gemm_tc_kernel<<<ggrid, 128, SMEM_DYN>>>(bias);

    scan_p1a_kernel<<<dim3(NCHUNK, BATCH), 512>>>();
    scan_p2_kernel<<<BATCH, 512>>>();
    scan_p1b_kernel<<<dim3(NCHUNK, BATCH), 512>>>(out);
}

// round 14
// speedup vs baseline: 6.6093x; 1.0539x over previous
#include <cuda_runtime.h>
#include <cuda_fp16.h>
#include <math.h>
#include <stdint.h>

#define BATCH 8
#define SEQ   4096
#define IN    256
#define GDIM  1536      // 2*OUT*3
#define KDIM  512       // WINDOW*IN
#define ODIM  512       // 2*OUT
#define M_TOTAL (BATCH*SEQ)   // 32768
#define NCHUNK 64
#define CLEN   64       // SEQ / NCHUNK

// ---- GEMM tiling ----
#define BM 128
#define BN 128
#define BK 32
#define NKT (KDIM / BK)        // 16 k-tiles
#define NSTAGE 4
// per-stage smem regions (bytes): A 8K | B 8K
#define R_A 0
#define R_B 8192
#define STAGE_BYTES 16384
#define SMEM_DYN (NSTAGE * STAGE_BYTES)

// ---- device scratch ----
__device__ __half  g_act[(size_t)M_TOTAL * GDIM];            // 100MB activated gates (fp16)
__device__ __half  g_xh [(size_t)M_TOTAL * IN];
__device__ __half  g_wh [(size_t)GDIM * KDIM];
__device__ float   g_A  [(size_t)BATCH * NCHUNK * ODIM];     // chunk f-product
__device__ float   g_B  [(size_t)BATCH * NCHUNK * ODIM];     // chunk local c end
__device__ float   g_C0 [(size_t)BATCH * NCHUNK * ODIM];     // chunk carry-in

// ---------------------------------------------------------------------------
// helpers
// ---------------------------------------------------------------------------
__device__ __forceinline__ uint32_t smem_u32(const void* p) {
    uint32_t a;
    asm("{ .reg .u64 t; cvta.to.shared.u64 t, %1; cvt.u32.u64 %0, t; }"
        : "=r"(a) : "l"(p));
    return a;
}

__device__ __forceinline__ void cp_async16(uint32_t dst, const void* src, int src_bytes) {
    asm volatile("cp.async.cg.shared.global [%0], [%1], 16, %2;"
                 :: "r"(dst), "l"(src), "r"(src_bytes));
}
__device__ __forceinline__ void cp_commit() {
    asm volatile("cp.async.commit_group;" ::: "memory");
}
template <int N>
__device__ __forceinline__ void cp_wait() {
    asm volatile("cp.async.wait_group %0;" :: "n"(N) : "memory");
}

__device__ __forceinline__ void ldsm_x4(unsigned* r, uint32_t addr) {
    asm volatile("ldmatrix.sync.aligned.m8n8.x4.shared.b16 {%0,%1,%2,%3}, [%4];"
                 : "=r"(r[0]), "=r"(r[1]), "=r"(r[2]), "=r"(r[3]) : "r"(addr));
}

__device__ __forceinline__ void mma16816h(float* d, const unsigned* a, const unsigned* b)
{
    asm volatile(
        "mma.sync.aligned.m16n8k16.row.col.f32.f16.f16.f32 "
        "{%0,%1,%2,%3}, {%4,%5,%6,%7}, {%8,%9}, {%0,%1,%2,%3};\n"
        : "+f"(d[0]), "+f"(d[1]), "+f"(d[2]), "+f"(d[3])
        : "r"(a[0]), "r"(a[1]), "r"(a[2]), "r"(a[3]), "r"(b[0]), "r"(b[1]));
}

__device__ __forceinline__ float fsigmoid(float t) {
    return __fdividef(1.f, 1.f + __expf(-t));
}
__device__ __forceinline__ float ftanh_fast(float t) {
    return __fmaf_rn(2.f, __fdividef(1.f, 1.f + __expf(-2.f * t)), -1.f);
}

// ---------------------------------------------------------------------------
// fp32 -> fp16 round
// ---------------------------------------------------------------------------
__global__ void round_kernel(const float* __restrict__ src,
                             __half* __restrict__ dst, int n4)
{
    int v = blockIdx.x * blockDim.x + threadIdx.x;
    if (v >= n4) return;
    float4 x = ((const float4*)src)[v];
    ushort4 hv = make_ushort4(__half_as_ushort(__float2half_rn(x.x)),
                              __half_as_ushort(__float2half_rn(x.y)),
                              __half_as_ushort(__float2half_rn(x.z)),
                              __half_as_ushort(__float2half_rn(x.w)));
    ((ushort4*)dst)[v] = hv;
}

// ---------------------------------------------------------------------------
// Tensor-core GEMM (single-pass fp16, f32 accum), 4-stage cp.async pipeline.
// Block 128x128, K-tile 32, 128 threads = 4 warps, warp tile 64m x 64n.
// smem layout per tile row: 32 elems (64B) = 4 x 16B chunks, chunk q stored
// at q ^ ((row>>1)&3)  (verified XOR-quarter swizzle).
// Gates stored as fp16.
// ---------------------------------------------------------------------------
__global__ __launch_bounds__(128)
void gemm_tc_kernel(const float* __restrict__ bias)
{
    extern __shared__ __align__(128) char dyn[];
    const uint32_t sbase = smem_u32(dyn);

    const int row0 = blockIdx.y * BM;
    const int col0 = blockIdx.x * BN;
    const int tid  = threadIdx.x;
    const int lane = tid & 31;
    const int w    = tid >> 5;
    const int wm   = (w & 1) * 64;     // warp m-offset
    const int wn   = (w >> 1) * 64;    // warp n-offset
    const int g    = lane >> 2;
    const int tig  = lane & 3;

    float acc[4][8][4];
    #pragma unroll
    for (int i = 0; i < 4; i++)
        #pragma unroll
        for (int j = 0; j < 8; j++)
            #pragma unroll
            for (int t = 0; t < 4; t++) acc[i][j][t] = 0.f;

    // ---- ldmatrix per-lane addressing ----
    const int lr = lane & 15;          // row within 16-row tile
    const int lc = lane >> 4;          // col-chunk select (0/1)
    uint32_t a_off[4]; int a_sw[4];
    #pragma unroll
    for (int mi = 0; mi < 4; mi++) {
        int m = wm + mi * 16 + lr;
        a_off[mi] = (uint32_t)m * 64;
        a_sw[mi]  = (m >> 1) & 3;
    }
    uint32_t b_off[4]; int b_sw[4];
    #pragma unroll
    for (int np = 0; np < 4; np++) {
        int n = wn + np * 16 + lr;
        b_off[np] = (uint32_t)n * 64;
        b_sw[np]  = (n >> 1) & 3;
    }

    // ---- cp.async loader: per k-tile, 4 slots/thread (A + B each) ----
    #define LOAD_STAGE(kt_, st_) do {                                         \
        const int  kg0     = (kt_) * BK;                                      \
        const bool shifted = (kg0 < IN);                                      \
        const int  kcol    = kg0 & (IN - 1);                                  \
        const uint32_t sb  = sbase + (st_) * STAGE_BYTES;                     \
        _Pragma("unroll")                                                     \
        for (int q = 0; q < 4; q++) {                                         \
            int slot = tid + q * 128;                                         \
            int m  = slot >> 2;                                               \
            int qu = slot & 3;                                                \
            int qs = qu ^ ((m >> 1) & 3);                                     \
            /* A */                                                           \
            int r  = row0 + m;                                                \
            int zb = (shifted && ((r & (SEQ - 1)) == 0)) ? 0 : 16;            \
            int rs = r - (shifted ? 1 : 0);                                   \
            if (!zb) rs = r;                                                  \
            size_t asrc = (size_t)rs * IN + kcol + qu * 8;                    \
            cp_async16(sb + R_A + m * 64 + qs * 16, g_xh + asrc, zb);         \
            /* B */                                                           \
            size_t bsrc = (size_t)(col0 + m) * KDIM + kg0 + qu * 8;           \
            cp_async16(sb + R_B + m * 64 + qs * 16, g_wh + bsrc, 16);         \
        }                                                                     \
    } while (0)

    // ---- prologue: prefetch k-tiles 0..2 ----
    LOAD_STAGE(0, 0); cp_commit();
    LOAD_STAGE(1, 1); cp_commit();
    LOAD_STAGE(2, 2); cp_commit();

    int st = 0;
    for (int kt = 0; kt < NKT; kt++) {
        cp_wait<2>();              // tile kt complete (kt+1, kt+2 may be in flight)
        __syncthreads();

        if (kt + 3 < NKT) {
            int st2 = st + 3; if (st2 >= NSTAGE) st2 -= NSTAGE;
            LOAD_STAGE(kt + 3, st2);
        }
        cp_commit();

        const uint32_t sb = sbase + st * STAGE_BYTES;

        #pragma unroll
        for (int j = 0; j < 2; j++) {
            const int kq = 2 * j + lc;     // 16B col-chunk for this lane
            unsigned ah[4][4], bb[8][2];
            #pragma unroll
            for (int mi = 0; mi < 4; mi++) {
                uint32_t ad = sb + R_A + a_off[mi] + (uint32_t)((kq ^ a_sw[mi]) << 4);
                ldsm_x4(ah[mi], ad);
            }
            #pragma unroll
            for (int np = 0; np < 4; np++) {
                unsigned t[4];
                uint32_t bd = sb + R_B + b_off[np] + (uint32_t)((kq ^ b_sw[np]) << 4);
                ldsm_x4(t, bd);
                bb[2 * np][0]     = t[0];
                bb[2 * np + 1][0] = t[1];
                bb[2 * np][1]     = t[2];
                bb[2 * np + 1][1] = t[3];
            }
            #pragma unroll
            for (int mi = 0; mi < 4; mi++)
                #pragma unroll
                for (int ni = 0; ni < 8; ni++)
                    mma16816h(acc[mi][ni], ah[mi], bb[ni]);
        }

        __syncthreads();
        st = st + 1; if (st >= NSTAGE) st = 0;
    }

    // ---- epilogue: bias + activation (block-uniform) + fp16 store ----
    const bool is_tanh = (col0 < 512);
    #pragma unroll
    for (int ni = 0; ni < 8; ni++) {
        int col = col0 + wn + ni * 8 + tig * 2;
        float b0 = bias[col], b1 = bias[col + 1];
        #pragma unroll
        for (int mi = 0; mi < 4; mi++) {
            int r0 = row0 + wm + mi * 16 + g;
            float v[4];
            v[0] = acc[mi][ni][0] + b0;
            v[1] = acc[mi][ni][1] + b1;
            v[2] = acc[mi][ni][2] + b0;
            v[3] = acc[mi][ni][3] + b1;
            #pragma unroll
            for (int t = 0; t < 4; t++)
                v[t] = is_tanh ? ftanh_fast(v[t]) : fsigmoid(v[t]);
            *(__half2*)&g_act[(size_t)r0 * GDIM + col]       = __floats2half2_rn(v[0], v[1]);
            *(__half2*)&g_act[(size_t)(r0 + 8) * GDIM + col] = __floats2half2_rn(v[2], v[3]);
        }
    }
}

// ---------------------------------------------------------------------------
// Scan phase 1a: chunk summary only.  P = prod(f), c_end (local scan, c0=0).
// Reads z,f only (fp16) -> 67MB.
// ---------------------------------------------------------------------------
__global__ __launch_bounds__(512)
void scan_p1a_kernel()
{
    const int ch = threadIdx.x;
    const int d  = ch >> 8;
    const int k  = blockIdx.x;
    const int b  = blockIdx.y;

    const int s0  = (k << 6) + (d ? (CLEN - 1) : 0);
    const int stp = d ? -1 : 1;
    const __half* gp = g_act + (size_t)(b * SEQ + s0) * GDIM;
    const ptrdiff_t gst = (ptrdiff_t)stp * GDIM;

    float c = 0.f, P = 1.f;
    #pragma unroll 4
    for (int i = 0; i < CLEN; i++) {
        float z = __half2float(gp[ch]);
        float f = __half2float(gp[512 + ch]);
        c = __fmaf_rn(f, c, __fmaf_rn(-f, z, z));
        P *= f;
        gp += gst;
    }
    size_t idx = (size_t)((b << 6) + k) * ODIM + ch;
    g_A[idx] = P;
    g_B[idx] = c;
}

// ---------------------------------------------------------------------------
// Scan phase 2: scan over chunk boundaries, stores carry-in per chunk.
// ---------------------------------------------------------------------------
__global__ __launch_bounds__(512)
void scan_p2_kernel()
{
    const int ch = threadIdx.x;
    const int d  = ch >> 8;
    const int b  = blockIdx.x;
    float c0 = 0.f;
    if (d == 0) {
        for (int k = 0; k < NCHUNK; k++) {
            size_t idx = (size_t)((b << 6) + k) * ODIM + ch;
            g_C0[idx] = c0;
            c0 = __fmaf_rn(g_A[idx], c0, g_B[idx]);
        }
    } else {
        for (int k = NCHUNK - 1; k >= 0; k--) {
            size_t idx = (size_t)((b << 6) + k) * ODIM + ch;
            g_C0[idx] = c0;
            c0 = __fmaf_rn(g_A[idx], c0, g_B[idx]);
        }
    }
}

// ---------------------------------------------------------------------------
// Scan phase 1b: final scan with carry-in, writes out directly.
// ---------------------------------------------------------------------------
__global__ __launch_bounds__(512)
void scan_p1b_kernel(float* __restrict__ out)
{
    const int ch = threadIdx.x;
    const int d  = ch >> 8;
    const int k  = blockIdx.x;
    const int b  = blockIdx.y;

    const int s0  = (k << 6) + (d ? (CLEN - 1) : 0);
    const int stp = d ? -1 : 1;
    const __half* gp = g_act + (size_t)(b * SEQ + s0) * GDIM;
    float* op = out + (size_t)(b * SEQ + s0) * ODIM + ch;
    const ptrdiff_t gst = (ptrdiff_t)stp * GDIM;
    const ptrdiff_t ost = (ptrdiff_t)stp * ODIM;

    float c = g_C0[(size_t)((b << 6) + k) * ODIM + ch];
    #pragma unroll 4
    for (int i = 0; i < CLEN; i++) {
        float z  = __half2float(gp[ch]);
        float f  = __half2float(gp[512 + ch]);
        float so = __half2float(gp[1024 + ch]);
        c = __fmaf_rn(f, c, __fmaf_rn(-f, z, z));
        *op = so * c;
        gp += gst; op += ost;
    }
}

extern "C" void kernel_launch(void* const* d_in, const int* in_sizes, int n_in,
                              void* d_out, int out_size)
{
    const float* x    = (const float*)d_in[0];  // (8, 4096, 256)
    const float* W    = (const float*)d_in[1];  // (1536, 512)
    const float* bias = (const float*)d_in[2];  // (1536,)
    float* out = (float*)d_out;                 // (8, 4096, 512)

    __half *xh, *wh;
    cudaGetSymbolAddress((void**)&xh, g_xh);
    cudaGetSymbolAddress((void**)&wh, g_wh);

    const int nx4 = (M_TOTAL * IN) / 4;
    const int nw4 = (GDIM * KDIM) / 4;
    round_kernel<<<(nx4 + 255) / 256, 256>>>(x, xh, nx4);
    round_kernel<<<(nw4 + 255) / 256, 256>>>(W, wh, nw4);

    cudaFuncSetAttribute(gemm_tc_kernel,
                         cudaFuncAttributeMaxDynamicSharedMemorySize, SMEM_DYN);
    dim3 ggrid(GDIM / BN, M_TOTAL / BM);        // (12, 256)
    gemm_tc_kernel<<<ggrid, 128, SMEM_DYN>>>(bias);

    scan_p1a_kernel<<<dim3(NCHUNK, BATCH), 512>>>();
    scan_p2_kernel<<<BATCH, 512>>>();
    scan_p1b_kernel<<<dim3(NCHUNK, BATCH), 512>>>(out);
}